// round 13
// baseline (speedup 1.0000x reference)
#include <cuda_runtime.h>
#include <math.h>
#include <stdint.h>

#define BB   8
#define NB   16          // batches per graph-pair set
#define NB2  32          // both chains merged (xyz batches 0-15, sem 16-31)
#define NPT  1024
#define KNN  20
#define NROW (NB*NPT)    // 16384
#define NROW2 (NB2*NPT)  // 32768
#define CH2  16          // batches per sequential dist/topk chunk in merged layers

// ------------------------------------------------------------------ packed fp32x2 helpers
__device__ __forceinline__ void ffma2(unsigned long long& d, unsigned long long a, unsigned long long b) {
    asm("fma.rn.f32x2 %0, %1, %2, %0;" : "+l"(d) : "l"(a), "l"(b));
}
__device__ __forceinline__ unsigned long long dup2(float x) {
    unsigned long long r;
    asm("mov.b64 %0, {%1, %1};" : "=l"(r) : "f"(x));
    return r;
}
__device__ __forceinline__ float2 unpk2(unsigned long long v) {
    float2 r;
    asm("mov.b64 {%0, %1}, %2;" : "=f"(r.x), "=f"(r.y) : "l"(v));
    return r;
}
__device__ __forceinline__ unsigned mapkey(float v) {
    unsigned u = __float_as_uint(v);
    return (u & 0x80000000u) ? ~u : (u | 0x80000000u);   // order-preserving; real keys > 0
}

// ------------------------------------------------------------------ scratch
__device__ unsigned g_neg[(size_t)NROW2*NPT];   // mapped-key distance matrix
__device__ int   g_idx[NROW2*KNN];
__device__ float g_xx [NROW2];
__device__ float g_x0 [NROW*4];
__device__ float g_s0 [NROW*128];
__device__ float g_hA [NROW2*64];
__device__ float g_hB [NROW2*64];
__device__ float g_h3 [NROW2*128];     // layer-3 out: xyz half then sem half
__device__ float g_emb[NROW*128];
__device__ float g_part[NB*8*128];
__device__ float g_gc  [NB*128];
__device__ float g_e   [NB*128];

// ------------------------------------------------------------------ transpose both inputs (B,C,N) -> point-major
__global__ void transpose_kernel(const float* __restrict__ f1, const float* __restrict__ f2,
                                 float* __restrict__ x0, float* __restrict__ s0) {
    int j = blockIdx.x * blockDim.x + threadIdx.x;
    int total = NB * 131 * NPT;
    if (j >= total) return;
    int n = j % NPT;
    int c = (j / NPT) % 131;
    int b = j / (131 * NPT);
    const float* in = (b < BB) ? f1 : f2;
    float v = in[((long)(b & 7) * 131 + c) * NPT + n];
    if (c < 3) {
        x0[(b*NPT + n)*4 + c] = v;
        if (c == 0) x0[(b*NPT + n)*4 + 3] = 0.0f;
    } else {
        s0[((long)(b*NPT) + n)*128 + (c - 3)] = v;
    }
}

// ------------------------------------------------------------------ per-point squared norm (NR rows)
template <int CROW, int NR>
__global__ void xx_kernel(const float* __restrict__ X, float* __restrict__ xx) {
    int j = blockIdx.x * 256 + threadIdx.x;
    if (j >= NR) return;
    const float* r = X + (long)j * CROW;
    float a = 0.f;
    #pragma unroll
    for (int c = 0; c < CROW; c++) a += r[c] * r[c];
    xx[j] = a;
}

// ------------------------------------------------------------------ fused KNN for C=4 (xyz layer 1)
// Whole batch (1024 pts * float4 = 16KB) + norms in smem; warp per row; register keys;
// fma chains replicate xx_kernel<4> and dist_kernel<4> exactly (ascending c, ((2a-xr)-xc)).
__global__ __launch_bounds__(512) void knn4_kernel(const float* __restrict__ X, int* __restrict__ idxout) {
    __shared__ float4 pts[NPT];
    __shared__ float xxc[NPT];
    int t = threadIdx.x;
    int warp = t >> 5, lane = t & 31;
    int b  = blockIdx.x / (NPT / 16);
    int r0 = (blockIdx.x % (NPT / 16)) * 16;
    const float4* Xb = (const float4*)(X + (long)b * NPT * 4);
    for (int i = t; i < NPT; i += 512) {
        float4 p = Xb[i];
        pts[i] = p;
        float a = 0.f;
        a = fmaf(p.x, p.x, a); a = fmaf(p.y, p.y, a);
        a = fmaf(p.z, p.z, a); a = fmaf(p.w, p.w, a);
        xxc[i] = a;
    }
    __syncthreads();
    long rowg = (long)(b * NPT) + r0 + warp;
    float4 rv = pts[r0 + warp];
    float xxr = xxc[r0 + warp];

    unsigned key[32];
    #pragma unroll
    for (int j = 0; j < 32; j++) {
        int col = lane + 32 * j;
        float4 pv = pts[col];
        float acc = 0.f;
        acc = fmaf(rv.x, pv.x, acc); acc = fmaf(rv.y, pv.y, acc);
        acc = fmaf(rv.z, pv.z, acc); acc = fmaf(rv.w, pv.w, acc);
        key[j] = mapkey(2.f * acc - xxr - xxc[col]);
    }

    // selection: REDUX argmax + per-lane sorted top-4 cache (gi = lane + 32*j)
    unsigned ck0=0,ck1=0,ck2=0,ck3=0;
    unsigned ci0=0,ci1=0,ci2=0,ci3=0;
    #pragma unroll
    for (int j = 0; j < 32; j++) {
        unsigned k = key[j];
        unsigned gi = (unsigned)(lane + 32*j);
        if (k > ck3) {
            if (k > ck0)      { ck3=ck2;ci3=ci2; ck2=ck1;ci2=ci1; ck1=ck0;ci1=ci0; ck0=k;ci0=gi; }
            else if (k > ck1) { ck3=ck2;ci3=ci2; ck2=ck1;ci2=ci1; ck1=k;ci1=gi; }
            else if (k > ck2) { ck3=ck2;ci3=ci2; ck2=k;ci2=gi; }
            else              { ck3=k;ci3=gi; }
        }
    }
    unsigned removed = 0u;   // bit j = gi>>5
    int navail = 4;
    for (int sel = 0; sel < KNN; sel++) {
        unsigned maxk = __reduce_max_sync(0xffffffffu, ck0);
        unsigned cand = (ck0 == maxk) ? ci0 : 0xffffffffu;
        unsigned widx = __reduce_min_sync(0xffffffffu, cand);
        if (lane == 0) idxout[rowg*KNN + sel] = (int)widx;
        if (ck0 == maxk && ci0 == widx) {        // unique owner ((widx&31)==lane)
            removed |= 1u << (widx >> 5);
            ck0=ck1;ci0=ci1; ck1=ck2;ci1=ci2; ck2=ck3;ci2=ci3; ck3=0;ci3=0;
            if (--navail == 0) {                  // rare refill from registers
                ck0=ck1=ck2=ck3=0; ci0=ci1=ci2=ci3=0;
                #pragma unroll
                for (int j = 0; j < 32; j++) {
                    if ((removed >> j) & 1u) continue;
                    unsigned k = key[j];
                    unsigned gi = (unsigned)(lane + 32*j);
                    if (k > ck3) {
                        if (k > ck0)      { ck3=ck2;ci3=ci2; ck2=ck1;ci2=ci1; ck1=ck0;ci1=ci0; ck0=k;ci0=gi; }
                        else if (k > ck1) { ck3=ck2;ci3=ci2; ck2=ck1;ci2=ci1; ck1=k;ci1=gi; }
                        else if (k > ck2) { ck3=ck2;ci3=ci2; ck2=k;ci2=gi; }
                        else              { ck3=k;ci3=gi; }
                    }
                }
                navail = 4;
            }
        }
    }
}

// ------------------------------------------------------------------ neg distance -> mapped u32 keys
// 128x128 tile, 256 threads, 8x8 register micro-tile, packed f32x2 FMA
template <int CROW>
__global__ __launch_bounds__(256, 1) void dist_kernel(const float* __restrict__ X,
                                                      const float* __restrict__ xx,
                                                      unsigned* __restrict__ neg) {
    constexpr int TC = (CROW < 16) ? CROW : 16;
    constexpr int LDW = 132;
    __shared__ float As[TC][LDW];
    __shared__ float Bs[TC][LDW];
    int b = blockIdx.z;
    int row0 = blockIdx.y * 128;
    int col0 = blockIdx.x * 128;
    int t = threadIdx.x;
    int tx = t & 15, ty = t >> 4;
    unsigned long long acc2[8][4];
    #pragma unroll
    for (int i = 0; i < 8; i++)
        #pragma unroll
        for (int j = 0; j < 4; j++) acc2[i][j] = 0ull;

    for (int c0 = 0; c0 < CROW; c0 += TC) {
        constexpr int NLD = (128 * TC) / 256;
        #pragma unroll
        for (int l = 0; l < NLD; l++) {
            int i = t + l * 256;
            int r = i / TC, c = i % TC;
            As[c][r] = X[((long)(b*NPT) + row0 + r) * CROW + c0 + c];
            Bs[c][r] = X[((long)(b*NPT) + col0 + r) * CROW + c0 + c];
        }
        __syncthreads();
        #pragma unroll
        for (int c = 0; c < TC; c++) {
            float4 a0 = *(const float4*)&As[c][ty*8];
            float4 a1 = *(const float4*)&As[c][ty*8+4];
            ulonglong2 b01 = *(const ulonglong2*)&Bs[c][tx*8];
            ulonglong2 b23 = *(const ulonglong2*)&Bs[c][tx*8+4];
            unsigned long long bp[4] = {b01.x, b01.y, b23.x, b23.y};
            unsigned long long ap[8];
            ap[0]=dup2(a0.x); ap[1]=dup2(a0.y); ap[2]=dup2(a0.z); ap[3]=dup2(a0.w);
            ap[4]=dup2(a1.x); ap[5]=dup2(a1.y); ap[6]=dup2(a1.z); ap[7]=dup2(a1.w);
            #pragma unroll
            for (int i = 0; i < 8; i++)
                #pragma unroll
                for (int j = 0; j < 4; j++) ffma2(acc2[i][j], ap[i], bp[j]);
        }
        __syncthreads();
    }
    float xr[8], xc[8];
    #pragma unroll
    for (int i = 0; i < 8; i++) {
        xr[i] = xx[b*NPT + row0 + ty*8 + i];
        xc[i] = xx[b*NPT + col0 + tx*8 + i];
    }
    #pragma unroll
    for (int i = 0; i < 8; i++) {
        long rbase = ((long)(b*NPT) + row0 + ty*8 + i) * NPT + col0 + tx*8;
        float2 p0 = unpk2(acc2[i][0]);
        float2 p1 = unpk2(acc2[i][1]);
        float2 p2 = unpk2(acc2[i][2]);
        float2 p3 = unpk2(acc2[i][3]);
        uint4 o0, o1;
        o0.x = mapkey(2.f*p0.x - xr[i] - xc[0]);
        o0.y = mapkey(2.f*p0.y - xr[i] - xc[1]);
        o0.z = mapkey(2.f*p1.x - xr[i] - xc[2]);
        o0.w = mapkey(2.f*p1.y - xr[i] - xc[3]);
        o1.x = mapkey(2.f*p2.x - xr[i] - xc[4]);
        o1.y = mapkey(2.f*p2.y - xr[i] - xc[5]);
        o1.z = mapkey(2.f*p3.x - xr[i] - xc[6]);
        o1.w = mapkey(2.f*p3.y - xr[i] - xc[7]);
        *(uint4*)&neg[rbase]     = o0;
        *(uint4*)&neg[rbase + 4] = o1;
    }
}

// ------------------------------------------------------------------ top-20: warp per row, REDUX argmax + per-lane top-4 cache
__global__ __launch_bounds__(256) void topk_kernel(const unsigned* __restrict__ neg, int* __restrict__ idxout) {
    int warp = threadIdx.x >> 5, lane = threadIdx.x & 31;
    long row = (long)blockIdx.x * 8 + warp;
    const unsigned* rp = neg + row * NPT;

    unsigned ck0=0,ck1=0,ck2=0,ck3=0;
    unsigned ci0=0,ci1=0,ci2=0,ci3=0;
    #pragma unroll
    for (int g = 0; g < 8; g++) {
        uint4 kv = *(const uint4*)&rp[g*128 + lane*4];
        unsigned kk[4] = {kv.x, kv.y, kv.z, kv.w};
        #pragma unroll
        for (int q = 0; q < 4; q++) {
            unsigned k = kk[q];
            unsigned gi = (unsigned)(g*128 + lane*4 + q);
            if (k > ck3) {
                if (k > ck0)      { ck3=ck2;ci3=ci2; ck2=ck1;ci2=ci1; ck1=ck0;ci1=ci0; ck0=k;ci0=gi; }
                else if (k > ck1) { ck3=ck2;ci3=ci2; ck2=ck1;ci2=ci1; ck1=k;ci1=gi; }
                else if (k > ck2) { ck3=ck2;ci3=ci2; ck2=k;ci2=gi; }
                else              { ck3=k;ci3=gi; }
            }
        }
    }
    unsigned removed = 0u;   // bit j = 4*g + q
    int navail = 4;
    for (int sel = 0; sel < KNN; sel++) {
        unsigned maxk = __reduce_max_sync(0xffffffffu, ck0);
        unsigned cand = (ck0 == maxk) ? ci0 : 0xffffffffu;
        unsigned widx = __reduce_min_sync(0xffffffffu, cand);
        if (lane == 0) idxout[row*KNN + sel] = (int)widx;
        if (ck0 == maxk && ci0 == widx) {        // unique owner
            int jw = (int)(((widx >> 7) << 2) | (widx & 3u));
            removed |= 1u << jw;
            ck0=ck1;ci0=ci1; ck1=ck2;ci1=ci2; ck2=ck3;ci2=ci3; ck3=0;ci3=0;
            if (--navail == 0) {                  // rare refill (lane needed 5+ wins)
                ck0=ck1=ck2=ck3=0; ci0=ci1=ci2=ci3=0;
                for (int g = 0; g < 8; g++) {
                    uint4 kv = *(const uint4*)&rp[g*128 + lane*4];
                    unsigned kk[4] = {kv.x, kv.y, kv.z, kv.w};
                    #pragma unroll
                    for (int q = 0; q < 4; q++) {
                        if ((removed >> (4*g + q)) & 1u) continue;
                        unsigned k = kk[q];
                        unsigned gi = (unsigned)(g*128 + lane*4 + q);
                        if (k > ck3) {
                            if (k > ck0)      { ck3=ck2;ci3=ci2; ck2=ck1;ci2=ci1; ck1=ck0;ci1=ci0; ck0=k;ci0=gi; }
                            else if (k > ck1) { ck3=ck2;ci3=ci2; ck2=ck1;ci2=ci1; ck1=k;ci1=gi; }
                            else if (k > ck2) { ck3=ck2;ci3=ci2; ck2=k;ci2=gi; }
                            else              { ck3=k;ci3=gi; }
                        }
                    }
                }
                navail = 4;
            }
        }
    }
}

// ------------------------------------------------------------------ fused gather + edge conv + BN + leaky + max_k  (c-paired FFMA2)
// dual weight sets: batches [0,NB) use set a, [NB,2NB) use set b
template <int CIN, int CROW, int COUT, int P, int THREADS, int NPH>
__global__ __launch_bounds__(THREADS, 1)
void conv_kernel(const float* __restrict__ X, const int* __restrict__ idx,
                 const float* __restrict__ w_a, const float* __restrict__ w_b,
                 const float* __restrict__ gam_a, const float* __restrict__ gam_b,
                 const float* __restrict__ bet_a, const float* __restrict__ bet_b,
                 float* __restrict__ out) {
    constexpr int TPP = THREADS / P;          // threads per point = COUT/2
    static_assert(TPP == COUT / 2, "CPT must be 2");
    constexpr int CPH = CROW / NPH;           // channels per phase
    constexpr int WST = CROW + 2;             // transposed weight row stride
    constexpr int CP  = CPH + 4;              // nb row stride
    extern __shared__ float sm[];
    float* w1T = sm;                          // [COUT][WST]
    float* wdT = w1T + COUT * WST;            // [COUT][WST]
    float* nb  = wdT + COUT * WST;            // [P][21][CP]
    int* sidx  = (int*)(nb + P * 21 * CP);    // [P][KNN]

    int t = threadIdx.x;
    int b  = blockIdx.x / (NPT / P);
    int n0 = (blockIdx.x % (NPT / P)) * P;
    const float* w   = (b < NB) ? w_a : w_b;
    const float* gam = (b < NB) ? gam_a : gam_b;
    const float* bet = (b < NB) ? bet_a : bet_b;

    for (int i = t; i < COUT * CROW; i += THREADS) {
        int o = i / CROW, c = i % CROW;
        float w1 = (c < CIN) ? w[o * (2*CIN) + c] : 0.f;
        float w2 = (c < CIN) ? w[o * (2*CIN) + CIN + c] : 0.f;
        w1T[o * WST + c] = w1;
        wdT[o * WST + c] = w2 - w1;
    }
    for (int i = t; i < P * KNN; i += THREADS)
        sidx[i] = idx[((long)(b*NPT) + n0) * KNN + i];
    __syncthreads();

    int p  = t / TPP;
    int o0 = t % TPP;
    int o1 = o0 + COUT / 2;
    unsigned long long s0[KNN], s1[KNN];
    unsigned long long u0 = 0ull, u1 = 0ull;
    #pragma unroll
    for (int k = 0; k < KNN; k++) { s0[k] = 0ull; s1[k] = 0ull; }

    const float* nbp = nb + p * 21 * CP;
    constexpr int V4 = CPH / 4;
    for (int ph = 0; ph < NPH; ph++) {
        if (ph > 0) __syncthreads();
        for (int i = t; i < P * 21 * V4; i += THREADS) {
            int c4 = i % V4;
            int vec = i / V4;
            int pp = vec / 21, k = vec % 21;
            int m = (k < KNN) ? sidx[pp*KNN + k] : (n0 + pp);
            float4 v = *(const float4*)&X[((long)(b*NPT) + m) * CROW + ph*CPH + 4*c4];
            *(float4*)&nb[(pp*21 + k) * CP + 4*c4] = v;
        }
        __syncthreads();

        #pragma unroll 1
        for (int c2 = 0; c2 < CPH/2; c2++) {
            int cl = 2 * c2;
            int cg = ph * CPH + cl;
            unsigned long long w1p0 = *(const unsigned long long*)&w1T[o0 * WST + cg];
            unsigned long long w1p1 = *(const unsigned long long*)&w1T[o1 * WST + cg];
            unsigned long long wdp0 = *(const unsigned long long*)&wdT[o0 * WST + cg];
            unsigned long long wdp1 = *(const unsigned long long*)&wdT[o1 * WST + cg];
            unsigned long long ctr = *(const unsigned long long*)&nbp[20 * CP + cl];
            ffma2(u0, wdp0, ctr);
            ffma2(u1, wdp1, ctr);
            #pragma unroll
            for (int k = 0; k < KNN; k++) {
                unsigned long long nbk = *(const unsigned long long*)&nbp[k * CP + cl];
                ffma2(s0[k], w1p0, nbk);
                ffma2(s1[k], w1p1, nbk);
            }
        }
    }

    float inv = rsqrtf(1.0f + 1e-5f);
    int n = n0 + p;
    float* op = &out[((long)(b*NPT) + n) * COUT];
    {
        float2 h = unpk2(s0[0]);
        float v0 = h.x + h.y;
        float mx = v0, mn = v0;
        #pragma unroll
        for (int k = 1; k < KNN; k++) {
            float2 hk = unpk2(s0[k]);
            float vk = hk.x + hk.y;
            mx = fmaxf(mx, vk); mn = fminf(mn, vk);
        }
        float2 up = unpk2(u0);
        float uu = up.x + up.y;
        float g = gam[o0], bt = bet[o0];
        float aa = g * inv;
        float base = ((aa >= 0.f) ? mx : mn) + uu;
        float v = aa * base + bt;
        op[o0] = v >= 0.f ? v : 0.2f * v;
    }
    {
        float2 h = unpk2(s1[0]);
        float v0 = h.x + h.y;
        float mx = v0, mn = v0;
        #pragma unroll
        for (int k = 1; k < KNN; k++) {
            float2 hk = unpk2(s1[k]);
            float vk = hk.x + hk.y;
            mx = fmaxf(mx, vk); mn = fminf(mn, vk);
        }
        float2 up = unpk2(u1);
        float uu = up.x + up.y;
        float g = gam[o1], bt = bet[o1];
        float aa = g * inv;
        float base = ((aa >= 0.f) ? mx : mn) + uu;
        float v = aa * base + bt;
        op[o1] = v >= 0.f ? v : 0.2f * v;
    }
}

// ------------------------------------------------------------------ ew conv on concat(H3,S3) -> emb (packed FMA)
__global__ __launch_bounds__(128)
void emb_kernel(const float* __restrict__ H3, const float* __restrict__ S3,
                const float* __restrict__ ew, const float* __restrict__ eg,
                const float* __restrict__ eb, float* __restrict__ emb) {
    extern __shared__ float sm[];
    float* wts  = sm;                 // [256][128]
    float* rows = wts + 256 * 128;    // [4][256]
    int t = threadIdx.x;
    for (int i = t; i < 256 * 128; i += 128) {
        int c = i / 128, o = i % 128;
        wts[c * 128 + o] = ew[o * 256 + c];
    }
    const int NITER = 8;
    int base = blockIdx.x * (4 * NITER);
    int pl = t / 32;
    int o4 = (t % 32) * 4;
    float inv = rsqrtf(1.0f + 1e-5f);
    for (int it = 0; it < NITER; it++) {
        __syncthreads();
        int p0 = base + it * 4;
        for (int i = t; i < 4 * 256; i += 128) {
            int pp = i / 256, c = i % 256;
            long pt = p0 + pp;
            rows[pp * 256 + c] = (c < 128) ? H3[pt * 128 + c] : S3[pt * 128 + c - 128];
        }
        __syncthreads();
        unsigned long long acc2[2] = {0ull, 0ull};
        for (int c = 0; c < 256; c++) {
            ulonglong2 wp = *(const ulonglong2*)&wts[c * 128 + o4];
            unsigned long long xd = dup2(rows[pl * 256 + c]);
            ffma2(acc2[0], wp.x, xd);
            ffma2(acc2[1], wp.y, xd);
        }
        float2 axy = unpk2(acc2[0]);
        float2 azw = unpk2(acc2[1]);
        float4 gmv = *(const float4*)&eg[o4];
        float4 btv = *(const float4*)&eb[o4];
        float4 r;
        { float v = gmv.x*inv*axy.x + btv.x; r.x = v>=0.f?v:0.2f*v; }
        { float v = gmv.y*inv*axy.y + btv.y; r.y = v>=0.f?v:0.2f*v; }
        { float v = gmv.z*inv*azw.x + btv.z; r.z = v>=0.f?v:0.2f*v; }
        { float v = gmv.w*inv*azw.y + btv.w; r.w = v>=0.f?v:0.2f*v; }
        long pt = p0 + pl;
        *(float4*)&emb[pt * 128 + o4] = r;
    }
}

// ------------------------------------------------------------------ attention pieces
__global__ void gcfused_kernel(const float* __restrict__ emb, const float* __restrict__ att_w,
                               float* __restrict__ gc) {
    __shared__ float part[8][128];
    __shared__ float es[128];
    int b = blockIdx.x, t = threadIdx.x;      // 1024 threads
    int seg = t >> 7, f = t & 127;
    const float* p = emb + ((long)(b*NPT) + seg*128) * 128 + f;
    float a = 0.f;
    #pragma unroll 4
    for (int n = 0; n < 128; n++) a += p[n * 128];
    part[seg][f] = a;
    __syncthreads();
    if (t < 128) {
        float s = 0.f;
        #pragma unroll
        for (int s8 = 0; s8 < 8; s8++) s += part[s8][t];
        es[t] = s;
    }
    __syncthreads();
    if (t < 128) {
        float gv = 0.f;
        for (int f2 = 0; f2 < 128; f2++) gv += es[f2] * att_w[f2 * 128 + t];
        gc[b * 128 + t] = tanhf(gv * (1.0f / NPT));
    }
}

__global__ void sc_kernel(const float* __restrict__ emb, const float* __restrict__ gc,
                          float* __restrict__ att) {
    int warp = threadIdx.x >> 5, lane = threadIdx.x & 31;
    int pid = blockIdx.x * 4 + warp;
    int b = pid >> 10;
    float a = 0.f;
    #pragma unroll
    for (int j = 0; j < 4; j++) {
        int f = lane + 32 * j;
        a += emb[(long)pid * 128 + f] * gc[b * 128 + f];
    }
    #pragma unroll
    for (int off = 16; off; off >>= 1) a += __shfl_down_sync(0xffffffffu, a, off);
    if (lane == 0) att[pid] = 1.0f / (1.0f + expf(-a));
}

__global__ void pool_part(const float* __restrict__ emb, const float* __restrict__ att,
                          float* __restrict__ part) {
    int b = blockIdx.x, seg = blockIdx.y, f = threadIdx.x;
    const float* p = emb + ((long)(b*NPT) + seg*128) * 128 + f;
    const float* aw = att + b*NPT + seg*128;
    float a = 0.f;
    #pragma unroll 4
    for (int n = 0; n < 128; n++) a += p[n * 128] * aw[n];
    part[(b*8 + seg) * 128 + f] = a;
}

__global__ void pool_fin(const float* __restrict__ part, float* __restrict__ e) {
    int b = blockIdx.x, t = threadIdx.x;
    float a = 0.f;
    #pragma unroll
    for (int s = 0; s < 8; s++) a += part[(b*8 + s) * 128 + t];
    e[b * 128 + t] = a;
}

// ------------------------------------------------------------------ final scoring
__global__ void final_kernel(const float* __restrict__ e, const float* __restrict__ tn_w,
                             const float* __restrict__ tn_wb, const float* __restrict__ tn_bias,
                             const float* __restrict__ fc1_w, const float* __restrict__ fc1_b,
                             const float* __restrict__ sc_w, const float* __restrict__ sc_b,
                             float* __restrict__ out) {
    __shared__ float e1s[128], e2s[128], red[128], ts[16], hs[16];
    int b = blockIdx.x, tid = threadIdx.x;
    e1s[tid] = e[b * 128 + tid];
    e2s[tid] = e[(b + 8) * 128 + tid];
    __syncthreads();
    for (int tt = 0; tt < 16; tt++) {
        float inner = 0.f;
        const float* wrow = tn_w + (long)tid * 128 * 16 + tt;
        for (int gI = 0; gI < 128; gI++) inner += wrow[gI * 16] * e2s[gI];
        red[tid] = e1s[tid] * inner;
        __syncthreads();
        for (int s2 = 64; s2; s2 >>= 1) {
            if (tid < s2) red[tid] += red[tid + s2];
            __syncthreads();
        }
        if (tid == 0) ts[tt] = red[0];
        __syncthreads();
    }
    if (tid < 16) {
        float blk = 0.f;
        for (int c = 0; c < 128; c++) blk += tn_wb[tid * 256 + c] * e1s[c];
        for (int c = 0; c < 128; c++) blk += tn_wb[tid * 256 + 128 + c] * e2s[c];
        float v = ts[tid] + blk + tn_bias[tid];
        ts[tid] = v > 0.f ? v : 0.f;
    }
    __syncthreads();
    if (tid < 16) {
        float h = fc1_b[tid];
        for (int u2 = 0; u2 < 16; u2++) h += fc1_w[tid * 16 + u2] * ts[u2];
        hs[tid] = h > 0.f ? h : 0.f;
    }
    __syncthreads();
    if (tid == 0) {
        float z = sc_b[0];
        for (int u2 = 0; u2 < 16; u2++) z += sc_w[u2] * hs[u2];
        out[b] = 1.0f / (1.0f + expf(-z));
    }
}

// ------------------------------------------------------------------ host
template <typename T>
static float* symaddr(T& sym_) {
    void* p = nullptr;
    cudaGetSymbolAddress(&p, sym_);
    return (float*)p;
}

extern "C" void kernel_launch(void* const* d_in, const int* in_sizes, int n_in,
                              void* d_out, int out_size) {
    (void)in_sizes; (void)n_in; (void)out_size;
    const float* f1    = (const float*)d_in[0];
    const float* f2    = (const float*)d_in[1];
    const float* sw1   = (const float*)d_in[2];
    const float* sg1   = (const float*)d_in[3];
    const float* sb1   = (const float*)d_in[4];
    const float* fw1   = (const float*)d_in[5];
    const float* fg1   = (const float*)d_in[6];
    const float* fb1   = (const float*)d_in[7];
    const float* sw2   = (const float*)d_in[8];
    const float* sg2   = (const float*)d_in[9];
    const float* sb2   = (const float*)d_in[10];
    const float* fw2   = (const float*)d_in[11];
    const float* fg2   = (const float*)d_in[12];
    const float* fb2   = (const float*)d_in[13];
    const float* sw3   = (const float*)d_in[14];
    const float* sg3   = (const float*)d_in[15];
    const float* sb3   = (const float*)d_in[16];
    const float* fw3   = (const float*)d_in[17];
    const float* fg3   = (const float*)d_in[18];
    const float* fb3   = (const float*)d_in[19];
    const float* ew    = (const float*)d_in[20];
    const float* eg    = (const float*)d_in[21];
    const float* ebv   = (const float*)d_in[22];
    const float* att_w = (const float*)d_in[23];
    const float* tn_w  = (const float*)d_in[24];
    const float* tn_wb = (const float*)d_in[25];
    const float* tn_b  = (const float*)d_in[26];
    const float* fc1_w = (const float*)d_in[27];
    const float* fc1_b = (const float*)d_in[28];
    const float* sc_w  = (const float*)d_in[29];
    const float* sc_b  = (const float*)d_in[30];
    float* out = (float*)d_out;

    unsigned* negp = (unsigned*)symaddr(g_neg);
    int*   idxp  = (int*)symaddr(g_idx);
    float* xxp   = symaddr(g_xx);
    float* x0p   = symaddr(g_x0);
    float* s0p   = symaddr(g_s0);
    float* hAp   = symaddr(g_hA);
    float* hBp   = symaddr(g_hB);
    float* h3p   = symaddr(g_h3);
    float* embp  = symaddr(g_emb);
    float* partp = symaddr(g_part);
    float* gcp   = symaddr(g_gc);
    float* ep    = symaddr(g_e);

    const int SM_C1 = (2*64*6    + 8*21*8 ) * 4 + 8*KNN*4;    // conv<3,4,64,8,256,1>
    const int SM_C2 = (2*64*66   + 8*21*68) * 4 + 8*KNN*4;    // conv<64,64,64,8,256,1>
    const int SM_C3 = (2*128*66  + 8*21*68) * 4 + 8*KNN*4;    // conv<64,64,128,8,512,1>
    const int SM_C4 = (2*64*130  + 16*21*68) * 4 + 16*KNN*4;  // conv<128,128,64,16,512,2>
    const int SM_EW = (256*128 + 4*256) * 4;

    cudaFuncSetAttribute(conv_kernel<64,64,64,8,256,1>,    cudaFuncAttributeMaxDynamicSharedMemorySize, SM_C2);
    cudaFuncSetAttribute(conv_kernel<64,64,128,8,512,1>,   cudaFuncAttributeMaxDynamicSharedMemorySize, SM_C3);
    cudaFuncSetAttribute(conv_kernel<128,128,64,16,512,2>, cudaFuncAttributeMaxDynamicSharedMemorySize, SM_C4);
    cudaFuncSetAttribute(emb_kernel,                       cudaFuncAttributeMaxDynamicSharedMemorySize, SM_EW);

    static cudaStream_t sB = 0;
    static cudaEvent_t evFork = 0, evJoin = 0;
    if (!sB) {
        cudaStreamCreateWithFlags(&sB, cudaStreamNonBlocking);
        cudaEventCreateWithFlags(&evFork, cudaEventDisableTiming);
        cudaEventCreateWithFlags(&evJoin, cudaEventDisableTiming);
    }

    transpose_kernel<<<(NB*131*NPT + 255) / 256, 256>>>(f1, f2, x0p, s0p);
    cudaEventRecord(evFork, 0);
    cudaStreamWaitEvent(sB, evFork, 0);

    // ---- layer 1: xyz fused KNN on stream 0, sem chain on stream sB (parallel) ----
    knn4_kernel<<<NROW/16, 512>>>(x0p, idxp);
    conv_kernel<3,4,64,8,256,1><<<NB*NPT/8, 256, SM_C1>>>(x0p, idxp, sw1, sw1, sg1, sg1, sb1, sb1, hAp);

    xx_kernel<128,NROW><<<NROW/256, 256, 0, sB>>>(s0p, xxp + NROW);
    dist_kernel<128><<<dim3(8,8,NB), 256, 0, sB>>>(s0p, xxp + NROW, negp + (size_t)NROW*NPT);
    topk_kernel<<<NROW/8, 256, 0, sB>>>(negp + (size_t)NROW*NPT, idxp + NROW*KNN);
    conv_kernel<128,128,64,16,512,2><<<NB*NPT/16, 512, SM_C4, sB>>>(s0p, idxp + NROW*KNN, fw1, fw1, fg1, fg1, fb1, fb1, hAp + NROW*64);

    cudaEventRecord(evJoin, sB);
    cudaStreamWaitEvent(0, evJoin, 0);

    // ---- layer 2 (merged NB2, 64 -> 64), sequential L2-blocked dist->topk chunks ----
    xx_kernel<64,NROW2><<<NROW2/256, 256>>>(hAp, xxp);
    for (int i = 0; i < 2; i++) {
        size_t boff = (size_t)CH2 * i * NPT;
        dist_kernel<64><<<dim3(8,8,CH2), 256>>>(hAp + boff*64, xxp + boff, negp + boff*NPT);
        topk_kernel<<<CH2*NPT/8, 256>>>(negp + boff*NPT, idxp + boff*KNN);
    }
    conv_kernel<64,64,64,8,256,1><<<NB2*NPT/8, 256, SM_C2>>>(hAp, idxp, sw2, fw2, sg2, fg2, sb2, fb2, hBp);

    // ---- layer 3 (merged NB2, 64 -> 128), sequential L2-blocked dist->topk chunks ----
    xx_kernel<64,NROW2><<<NROW2/256, 256>>>(hBp, xxp);
    for (int i = 0; i < 2; i++) {
        size_t boff = (size_t)CH2 * i * NPT;
        dist_kernel<64><<<dim3(8,8,CH2), 256>>>(hBp + boff*64, xxp + boff, negp + boff*NPT);
        topk_kernel<<<CH2*NPT/8, 256>>>(negp + boff*NPT, idxp + boff*KNN);
    }
    conv_kernel<64,64,128,8,512,1><<<NB2*NPT/8, 512, SM_C3>>>(hBp, idxp, sw3, fw3, sg3, fg3, sb3, fb3, h3p);

    // ---- fuse + attention (all 16 batches) ----
    emb_kernel<<<NROW/32, 128, SM_EW>>>(h3p, h3p + NROW*128, ew, eg, ebv, embp);

    float* att_out = out + 8;                       // att1 (b 0..7) then att2 (b 8..15), contiguous
    gcfused_kernel<<<NB, 1024>>>(embp, att_w, gcp);
    sc_kernel<<<NROW/4, 128>>>(embp, gcp, att_out);
    pool_part<<<dim3(NB, 8), 128>>>(embp, att_out, partp);
    pool_fin<<<NB, 128>>>(partp, ep);

    final_kernel<<<BB, 128>>>(ep, tn_w, tn_wb, tn_b, fc1_w, fc1_b, sc_w, sc_b, out);
}

// round 14
// speedup vs baseline: 1.0383x; 1.0383x over previous
#include <cuda_runtime.h>
#include <math.h>
#include <stdint.h>

#define BB   8
#define NB   16          // batches per graph-pair set
#define NB2  32          // both chains merged (xyz batches 0-15, sem 16-31)
#define NPT  1024
#define KNN  20
#define NROW (NB*NPT)    // 16384
#define NROW2 (NB2*NPT)  // 32768

// ------------------------------------------------------------------ packed fp32x2 helpers
__device__ __forceinline__ void ffma2(unsigned long long& d, unsigned long long a, unsigned long long b) {
    asm("fma.rn.f32x2 %0, %1, %2, %0;" : "+l"(d) : "l"(a), "l"(b));
}
__device__ __forceinline__ unsigned long long dup2(float x) {
    unsigned long long r;
    asm("mov.b64 %0, {%1, %1};" : "=l"(r) : "f"(x));
    return r;
}
__device__ __forceinline__ float2 unpk2(unsigned long long v) {
    float2 r;
    asm("mov.b64 {%0, %1}, %2;" : "=f"(r.x), "=f"(r.y) : "l"(v));
    return r;
}
__device__ __forceinline__ unsigned mapkey(float v) {
    unsigned u = __float_as_uint(v);
    return (u & 0x80000000u) ? ~u : (u | 0x80000000u);   // order-preserving; real keys > 0
}

// ------------------------------------------------------------------ scratch
__device__ unsigned g_neg[(size_t)NROW2*NPT];   // mapped-key distance matrix
__device__ int   g_idx[NROW2*KNN];
__device__ float g_xx [NROW2];
__device__ float g_x0 [NROW*4];
__device__ float g_s0 [NROW*128];
__device__ float g_hA [NROW2*64];
__device__ float g_hB [NROW2*64];
__device__ float g_h3 [NROW2*128];     // layer-3 out: xyz half then sem half
__device__ float g_emb[NROW*128];
__device__ float g_part[NB*8*128];
__device__ float g_gc  [NB*128];
__device__ float g_e   [NB*128];

// ------------------------------------------------------------------ transposes
// xyz: small, simple (reads coalesced along n)
__global__ void transposeX_kernel(const float* __restrict__ f1, const float* __restrict__ f2,
                                  float* __restrict__ x0) {
    int j = blockIdx.x * blockDim.x + threadIdx.x;     // over NB*3*NPT
    if (j >= NB * 3 * NPT) return;
    int n = j % NPT;
    int c = (j / NPT) % 3;
    int b = j / (3 * NPT);
    const float* in = (b < BB) ? f1 : f2;
    float v = in[((long)(b & 7) * 131 + c) * NPT + n];
    x0[(b*NPT + n)*4 + c] = v;
    if (c == 0) x0[(b*NPT + n)*4 + 3] = 0.0f;
}
// sem: 32x32 smem-tiled transpose, both sides coalesced
__global__ void transposeS_kernel(const float* __restrict__ f1, const float* __restrict__ f2,
                                  float* __restrict__ s0) {
    __shared__ float tile[32][33];
    int b  = blockIdx.z;
    int c0 = blockIdx.y * 32;          // channel block within [0,128)
    int n0 = blockIdx.x * 32;          // point block
    const float* in = (b < BB) ? f1 : f2;
    int tx = threadIdx.x, ty = threadIdx.y;   // 32 x 8
    #pragma unroll
    for (int i = 0; i < 32; i += 8)
        tile[ty + i][tx] = in[((long)(b & 7) * 131 + 3 + c0 + ty + i) * NPT + n0 + tx];
    __syncthreads();
    #pragma unroll
    for (int i = 0; i < 32; i += 8)
        s0[((long)(b*NPT) + n0 + ty + i) * 128 + c0 + tx] = tile[tx][ty + i];
}

// ------------------------------------------------------------------ per-point squared norm (float4 + 4 partial chains)
template <int CROW, int NR>
__global__ void xx_kernel(const float* __restrict__ X, float* __restrict__ xx) {
    int j = blockIdx.x * 256 + threadIdx.x;
    if (j >= NR) return;
    const float4* r = (const float4*)(X + (long)j * CROW);
    float a0 = 0.f, a1 = 0.f, a2 = 0.f, a3 = 0.f;
    #pragma unroll
    for (int c = 0; c < CROW / 4; c++) {
        float4 v = r[c];
        a0 = fmaf(v.x, v.x, a0);
        a1 = fmaf(v.y, v.y, a1);
        a2 = fmaf(v.z, v.z, a2);
        a3 = fmaf(v.w, v.w, a3);
    }
    xx[j] = (a0 + a1) + (a2 + a3);
}

// ------------------------------------------------------------------ fused KNN for C=4 (xyz layer 1)
__global__ __launch_bounds__(512) void knn4_kernel(const float* __restrict__ X, int* __restrict__ idxout) {
    __shared__ float4 pts[NPT];
    __shared__ float xxc[NPT];
    int t = threadIdx.x;
    int warp = t >> 5, lane = t & 31;
    int b  = blockIdx.x / (NPT / 16);
    int r0 = (blockIdx.x % (NPT / 16)) * 16;
    const float4* Xb = (const float4*)(X + (long)b * NPT * 4);
    for (int i = t; i < NPT; i += 512) {
        float4 p = Xb[i];
        pts[i] = p;
        float a = 0.f;
        a = fmaf(p.x, p.x, a); a = fmaf(p.y, p.y, a);
        a = fmaf(p.z, p.z, a); a = fmaf(p.w, p.w, a);
        xxc[i] = a;
    }
    __syncthreads();
    long rowg = (long)(b * NPT) + r0 + warp;
    float4 rv = pts[r0 + warp];
    float xxr = xxc[r0 + warp];

    unsigned key[32];
    #pragma unroll
    for (int j = 0; j < 32; j++) {
        int col = lane + 32 * j;
        float4 pv = pts[col];
        float acc = 0.f;
        acc = fmaf(rv.x, pv.x, acc); acc = fmaf(rv.y, pv.y, acc);
        acc = fmaf(rv.z, pv.z, acc); acc = fmaf(rv.w, pv.w, acc);
        key[j] = mapkey(2.f * acc - xxr - xxc[col]);
    }

    unsigned ck0=0,ck1=0,ck2=0,ck3=0;
    unsigned ci0=0,ci1=0,ci2=0,ci3=0;
    #pragma unroll
    for (int j = 0; j < 32; j++) {
        unsigned k = key[j];
        unsigned gi = (unsigned)(lane + 32*j);
        if (k > ck3) {
            if (k > ck0)      { ck3=ck2;ci3=ci2; ck2=ck1;ci2=ci1; ck1=ck0;ci1=ci0; ck0=k;ci0=gi; }
            else if (k > ck1) { ck3=ck2;ci3=ci2; ck2=ck1;ci2=ci1; ck1=k;ci1=gi; }
            else if (k > ck2) { ck3=ck2;ci3=ci2; ck2=k;ci2=gi; }
            else              { ck3=k;ci3=gi; }
        }
    }
    unsigned removed = 0u;
    int navail = 4;
    for (int sel = 0; sel < KNN; sel++) {
        unsigned maxk = __reduce_max_sync(0xffffffffu, ck0);
        unsigned cand = (ck0 == maxk) ? ci0 : 0xffffffffu;
        unsigned widx = __reduce_min_sync(0xffffffffu, cand);
        if (lane == 0) idxout[rowg*KNN + sel] = (int)widx;
        if (ck0 == maxk && ci0 == widx) {
            removed |= 1u << (widx >> 5);
            ck0=ck1;ci0=ci1; ck1=ck2;ci1=ci2; ck2=ck3;ci2=ci3; ck3=0;ci3=0;
            if (--navail == 0) {
                ck0=ck1=ck2=ck3=0; ci0=ci1=ci2=ci3=0;
                #pragma unroll
                for (int j = 0; j < 32; j++) {
                    if ((removed >> j) & 1u) continue;
                    unsigned k = key[j];
                    unsigned gi = (unsigned)(lane + 32*j);
                    if (k > ck3) {
                        if (k > ck0)      { ck3=ck2;ci3=ci2; ck2=ck1;ci2=ci1; ck1=ck0;ci1=ci0; ck0=k;ci0=gi; }
                        else if (k > ck1) { ck3=ck2;ci3=ci2; ck2=ck1;ci2=ci1; ck1=k;ci1=gi; }
                        else if (k > ck2) { ck3=ck2;ci3=ci2; ck2=k;ci2=gi; }
                        else              { ck3=k;ci3=gi; }
                    }
                }
                navail = 4;
            }
        }
    }
}

// ------------------------------------------------------------------ neg distance -> mapped u32 keys
template <int CROW>
__global__ __launch_bounds__(256, 1) void dist_kernel(const float* __restrict__ X,
                                                      const float* __restrict__ xx,
                                                      unsigned* __restrict__ neg) {
    constexpr int TC = (CROW < 16) ? CROW : 16;
    constexpr int LDW = 132;
    __shared__ float As[TC][LDW];
    __shared__ float Bs[TC][LDW];
    int b = blockIdx.z;
    int row0 = blockIdx.y * 128;
    int col0 = blockIdx.x * 128;
    int t = threadIdx.x;
    int tx = t & 15, ty = t >> 4;
    unsigned long long acc2[8][4];
    #pragma unroll
    for (int i = 0; i < 8; i++)
        #pragma unroll
        for (int j = 0; j < 4; j++) acc2[i][j] = 0ull;

    for (int c0 = 0; c0 < CROW; c0 += TC) {
        constexpr int NLD = (128 * TC) / 256;
        #pragma unroll
        for (int l = 0; l < NLD; l++) {
            int i = t + l * 256;
            int r = i / TC, c = i % TC;
            As[c][r] = X[((long)(b*NPT) + row0 + r) * CROW + c0 + c];
            Bs[c][r] = X[((long)(b*NPT) + col0 + r) * CROW + c0 + c];
        }
        __syncthreads();
        #pragma unroll
        for (int c = 0; c < TC; c++) {
            float4 a0 = *(const float4*)&As[c][ty*8];
            float4 a1 = *(const float4*)&As[c][ty*8+4];
            ulonglong2 b01 = *(const ulonglong2*)&Bs[c][tx*8];
            ulonglong2 b23 = *(const ulonglong2*)&Bs[c][tx*8+4];
            unsigned long long bp[4] = {b01.x, b01.y, b23.x, b23.y};
            unsigned long long ap[8];
            ap[0]=dup2(a0.x); ap[1]=dup2(a0.y); ap[2]=dup2(a0.z); ap[3]=dup2(a0.w);
            ap[4]=dup2(a1.x); ap[5]=dup2(a1.y); ap[6]=dup2(a1.z); ap[7]=dup2(a1.w);
            #pragma unroll
            for (int i = 0; i < 8; i++)
                #pragma unroll
                for (int j = 0; j < 4; j++) ffma2(acc2[i][j], ap[i], bp[j]);
        }
        __syncthreads();
    }
    float xr[8], xc[8];
    #pragma unroll
    for (int i = 0; i < 8; i++) {
        xr[i] = xx[b*NPT + row0 + ty*8 + i];
        xc[i] = xx[b*NPT + col0 + tx*8 + i];
    }
    #pragma unroll
    for (int i = 0; i < 8; i++) {
        long rbase = ((long)(b*NPT) + row0 + ty*8 + i) * NPT + col0 + tx*8;
        float2 p0 = unpk2(acc2[i][0]);
        float2 p1 = unpk2(acc2[i][1]);
        float2 p2 = unpk2(acc2[i][2]);
        float2 p3 = unpk2(acc2[i][3]);
        uint4 o0, o1;
        o0.x = mapkey(2.f*p0.x - xr[i] - xc[0]);
        o0.y = mapkey(2.f*p0.y - xr[i] - xc[1]);
        o0.z = mapkey(2.f*p1.x - xr[i] - xc[2]);
        o0.w = mapkey(2.f*p1.y - xr[i] - xc[3]);
        o1.x = mapkey(2.f*p2.x - xr[i] - xc[4]);
        o1.y = mapkey(2.f*p2.y - xr[i] - xc[5]);
        o1.z = mapkey(2.f*p3.x - xr[i] - xc[6]);
        o1.w = mapkey(2.f*p3.y - xr[i] - xc[7]);
        *(uint4*)&neg[rbase]     = o0;
        *(uint4*)&neg[rbase + 4] = o1;
    }
}

// ------------------------------------------------------------------ top-20: warp per row, REDUX argmax + per-lane top-4 cache
__global__ __launch_bounds__(256) void topk_kernel(const unsigned* __restrict__ neg, int* __restrict__ idxout) {
    int warp = threadIdx.x >> 5, lane = threadIdx.x & 31;
    long row = (long)blockIdx.x * 8 + warp;
    const unsigned* rp = neg + row * NPT;

    unsigned ck0=0,ck1=0,ck2=0,ck3=0;
    unsigned ci0=0,ci1=0,ci2=0,ci3=0;
    #pragma unroll
    for (int g = 0; g < 8; g++) {
        uint4 kv = *(const uint4*)&rp[g*128 + lane*4];
        unsigned kk[4] = {kv.x, kv.y, kv.z, kv.w};
        #pragma unroll
        for (int q = 0; q < 4; q++) {
            unsigned k = kk[q];
            unsigned gi = (unsigned)(g*128 + lane*4 + q);
            if (k > ck3) {
                if (k > ck0)      { ck3=ck2;ci3=ci2; ck2=ck1;ci2=ci1; ck1=ck0;ci1=ci0; ck0=k;ci0=gi; }
                else if (k > ck1) { ck3=ck2;ci3=ci2; ck2=ck1;ci2=ci1; ck1=k;ci1=gi; }
                else if (k > ck2) { ck3=ck2;ci3=ci2; ck2=k;ci2=gi; }
                else              { ck3=k;ci3=gi; }
            }
        }
    }
    unsigned removed = 0u;   // bit j = 4*g + q
    int navail = 4;
    for (int sel = 0; sel < KNN; sel++) {
        unsigned maxk = __reduce_max_sync(0xffffffffu, ck0);
        unsigned cand = (ck0 == maxk) ? ci0 : 0xffffffffu;
        unsigned widx = __reduce_min_sync(0xffffffffu, cand);
        if (lane == 0) idxout[row*KNN + sel] = (int)widx;
        if (ck0 == maxk && ci0 == widx) {
            int jw = (int)(((widx >> 7) << 2) | (widx & 3u));
            removed |= 1u << jw;
            ck0=ck1;ci0=ci1; ck1=ck2;ci1=ci2; ck2=ck3;ci2=ci3; ck3=0;ci3=0;
            if (--navail == 0) {
                ck0=ck1=ck2=ck3=0; ci0=ci1=ci2=ci3=0;
                for (int g = 0; g < 8; g++) {
                    uint4 kv = *(const uint4*)&rp[g*128 + lane*4];
                    unsigned kk[4] = {kv.x, kv.y, kv.z, kv.w};
                    #pragma unroll
                    for (int q = 0; q < 4; q++) {
                        if ((removed >> (4*g + q)) & 1u) continue;
                        unsigned k = kk[q];
                        unsigned gi = (unsigned)(g*128 + lane*4 + q);
                        if (k > ck3) {
                            if (k > ck0)      { ck3=ck2;ci3=ci2; ck2=ck1;ci2=ci1; ck1=ck0;ci1=ci0; ck0=k;ci0=gi; }
                            else if (k > ck1) { ck3=ck2;ci3=ci2; ck2=ck1;ci2=ci1; ck1=k;ci1=gi; }
                            else if (k > ck2) { ck3=ck2;ci3=ci2; ck2=k;ci2=gi; }
                            else              { ck3=k;ci3=gi; }
                        }
                    }
                }
                navail = 4;
            }
        }
    }
}

// ------------------------------------------------------------------ fused gather + edge conv + BN + leaky + max_k  (c-paired FFMA2)
template <int CIN, int CROW, int COUT, int P, int THREADS, int NPH>
__global__ __launch_bounds__(THREADS, 1)
void conv_kernel(const float* __restrict__ X, const int* __restrict__ idx,
                 const float* __restrict__ w_a, const float* __restrict__ w_b,
                 const float* __restrict__ gam_a, const float* __restrict__ gam_b,
                 const float* __restrict__ bet_a, const float* __restrict__ bet_b,
                 float* __restrict__ out) {
    constexpr int TPP = THREADS / P;
    static_assert(TPP == COUT / 2, "CPT must be 2");
    constexpr int CPH = CROW / NPH;
    constexpr int WST = CROW + 2;
    constexpr int CP  = CPH + 4;
    extern __shared__ float sm[];
    float* w1T = sm;
    float* wdT = w1T + COUT * WST;
    float* nb  = wdT + COUT * WST;
    int* sidx  = (int*)(nb + P * 21 * CP);

    int t = threadIdx.x;
    int b  = blockIdx.x / (NPT / P);
    int n0 = (blockIdx.x % (NPT / P)) * P;
    const float* w   = (b < NB) ? w_a : w_b;
    const float* gam = (b < NB) ? gam_a : gam_b;
    const float* bet = (b < NB) ? bet_a : bet_b;

    for (int i = t; i < COUT * CROW; i += THREADS) {
        int o = i / CROW, c = i % CROW;
        float w1 = (c < CIN) ? w[o * (2*CIN) + c] : 0.f;
        float w2 = (c < CIN) ? w[o * (2*CIN) + CIN + c] : 0.f;
        w1T[o * WST + c] = w1;
        wdT[o * WST + c] = w2 - w1;
    }
    for (int i = t; i < P * KNN; i += THREADS)
        sidx[i] = idx[((long)(b*NPT) + n0) * KNN + i];
    __syncthreads();

    int p  = t / TPP;
    int o0 = t % TPP;
    int o1 = o0 + COUT / 2;
    unsigned long long s0[KNN], s1[KNN];
    unsigned long long u0 = 0ull, u1 = 0ull;
    #pragma unroll
    for (int k = 0; k < KNN; k++) { s0[k] = 0ull; s1[k] = 0ull; }

    const float* nbp = nb + p * 21 * CP;
    constexpr int V4 = CPH / 4;
    for (int ph = 0; ph < NPH; ph++) {
        if (ph > 0) __syncthreads();
        for (int i = t; i < P * 21 * V4; i += THREADS) {
            int c4 = i % V4;
            int vec = i / V4;
            int pp = vec / 21, k = vec % 21;
            int m = (k < KNN) ? sidx[pp*KNN + k] : (n0 + pp);
            float4 v = *(const float4*)&X[((long)(b*NPT) + m) * CROW + ph*CPH + 4*c4];
            *(float4*)&nb[(pp*21 + k) * CP + 4*c4] = v;
        }
        __syncthreads();

        #pragma unroll 1
        for (int c2 = 0; c2 < CPH/2; c2++) {
            int cl = 2 * c2;
            int cg = ph * CPH + cl;
            unsigned long long w1p0 = *(const unsigned long long*)&w1T[o0 * WST + cg];
            unsigned long long w1p1 = *(const unsigned long long*)&w1T[o1 * WST + cg];
            unsigned long long wdp0 = *(const unsigned long long*)&wdT[o0 * WST + cg];
            unsigned long long wdp1 = *(const unsigned long long*)&wdT[o1 * WST + cg];
            unsigned long long ctr = *(const unsigned long long*)&nbp[20 * CP + cl];
            ffma2(u0, wdp0, ctr);
            ffma2(u1, wdp1, ctr);
            #pragma unroll
            for (int k = 0; k < KNN; k++) {
                unsigned long long nbk = *(const unsigned long long*)&nbp[k * CP + cl];
                ffma2(s0[k], w1p0, nbk);
                ffma2(s1[k], w1p1, nbk);
            }
        }
    }

    float inv = rsqrtf(1.0f + 1e-5f);
    int n = n0 + p;
    float* op = &out[((long)(b*NPT) + n) * COUT];
    {
        float2 h = unpk2(s0[0]);
        float v0 = h.x + h.y;
        float mx = v0, mn = v0;
        #pragma unroll
        for (int k = 1; k < KNN; k++) {
            float2 hk = unpk2(s0[k]);
            float vk = hk.x + hk.y;
            mx = fmaxf(mx, vk); mn = fminf(mn, vk);
        }
        float2 up = unpk2(u0);
        float uu = up.x + up.y;
        float g = gam[o0], bt = bet[o0];
        float aa = g * inv;
        float base = ((aa >= 0.f) ? mx : mn) + uu;
        float v = aa * base + bt;
        op[o0] = v >= 0.f ? v : 0.2f * v;
    }
    {
        float2 h = unpk2(s1[0]);
        float v0 = h.x + h.y;
        float mx = v0, mn = v0;
        #pragma unroll
        for (int k = 1; k < KNN; k++) {
            float2 hk = unpk2(s1[k]);
            float vk = hk.x + hk.y;
            mx = fmaxf(mx, vk); mn = fminf(mn, vk);
        }
        float2 up = unpk2(u1);
        float uu = up.x + up.y;
        float g = gam[o1], bt = bet[o1];
        float aa = g * inv;
        float base = ((aa >= 0.f) ? mx : mn) + uu;
        float v = aa * base + bt;
        op[o1] = v >= 0.f ? v : 0.2f * v;
    }
}

// ------------------------------------------------------------------ ew conv on concat(H3,S3) -> emb (packed FMA)
__global__ __launch_bounds__(128)
void emb_kernel(const float* __restrict__ H3, const float* __restrict__ S3,
                const float* __restrict__ ew, const float* __restrict__ eg,
                const float* __restrict__ eb, float* __restrict__ emb) {
    extern __shared__ float sm[];
    float* wts  = sm;                 // [256][128]
    float* rows = wts + 256 * 128;    // [4][256]
    int t = threadIdx.x;
    for (int i = t; i < 256 * 128; i += 128) {
        int c = i / 128, o = i % 128;
        wts[c * 128 + o] = ew[o * 256 + c];
    }
    const int NITER = 8;
    int base = blockIdx.x * (4 * NITER);
    int pl = t / 32;
    int o4 = (t % 32) * 4;
    float inv = rsqrtf(1.0f + 1e-5f);
    for (int it = 0; it < NITER; it++) {
        __syncthreads();
        int p0 = base + it * 4;
        for (int i = t; i < 4 * 256; i += 128) {
            int pp = i / 256, c = i % 256;
            long pt = p0 + pp;
            rows[pp * 256 + c] = (c < 128) ? H3[pt * 128 + c] : S3[pt * 128 + c - 128];
        }
        __syncthreads();
        unsigned long long acc2[2] = {0ull, 0ull};
        for (int c = 0; c < 256; c++) {
            ulonglong2 wp = *(const ulonglong2*)&wts[c * 128 + o4];
            unsigned long long xd = dup2(rows[pl * 256 + c]);
            ffma2(acc2[0], wp.x, xd);
            ffma2(acc2[1], wp.y, xd);
        }
        float2 axy = unpk2(acc2[0]);
        float2 azw = unpk2(acc2[1]);
        float4 gmv = *(const float4*)&eg[o4];
        float4 btv = *(const float4*)&eb[o4];
        float4 r;
        { float v = gmv.x*inv*axy.x + btv.x; r.x = v>=0.f?v:0.2f*v; }
        { float v = gmv.y*inv*axy.y + btv.y; r.y = v>=0.f?v:0.2f*v; }
        { float v = gmv.z*inv*azw.x + btv.z; r.z = v>=0.f?v:0.2f*v; }
        { float v = gmv.w*inv*azw.y + btv.w; r.w = v>=0.f?v:0.2f*v; }
        long pt = p0 + pl;
        *(float4*)&emb[pt * 128 + o4] = r;
    }
}

// ------------------------------------------------------------------ attention pieces
__global__ void gcfused_kernel(const float* __restrict__ emb, const float* __restrict__ att_w,
                               float* __restrict__ gc) {
    __shared__ float part[8][128];
    __shared__ float es[128];
    int b = blockIdx.x, t = threadIdx.x;      // 1024 threads
    int seg = t >> 7, f = t & 127;
    const float* p = emb + ((long)(b*NPT) + seg*128) * 128 + f;
    float a = 0.f;
    #pragma unroll 4
    for (int n = 0; n < 128; n++) a += p[n * 128];
    part[seg][f] = a;
    __syncthreads();
    if (t < 128) {
        float s = 0.f;
        #pragma unroll
        for (int s8 = 0; s8 < 8; s8++) s += part[s8][t];
        es[t] = s;
    }
    __syncthreads();
    if (t < 128) {
        float gv = 0.f;
        for (int f2 = 0; f2 < 128; f2++) gv += es[f2] * att_w[f2 * 128 + t];
        gc[b * 128 + t] = tanhf(gv * (1.0f / NPT));
    }
}

__global__ void sc_kernel(const float* __restrict__ emb, const float* __restrict__ gc,
                          float* __restrict__ att) {
    int warp = threadIdx.x >> 5, lane = threadIdx.x & 31;
    int pid = blockIdx.x * 4 + warp;
    int b = pid >> 10;
    float a = 0.f;
    #pragma unroll
    for (int j = 0; j < 4; j++) {
        int f = lane + 32 * j;
        a += emb[(long)pid * 128 + f] * gc[b * 128 + f];
    }
    #pragma unroll
    for (int off = 16; off; off >>= 1) a += __shfl_down_sync(0xffffffffu, a, off);
    if (lane == 0) att[pid] = 1.0f / (1.0f + expf(-a));
}

__global__ void pool_part(const float* __restrict__ emb, const float* __restrict__ att,
                          float* __restrict__ part) {
    int b = blockIdx.x, seg = blockIdx.y, f = threadIdx.x;
    const float* p = emb + ((long)(b*NPT) + seg*128) * 128 + f;
    const float* aw = att + b*NPT + seg*128;
    float a = 0.f;
    #pragma unroll 4
    for (int n = 0; n < 128; n++) a += p[n * 128] * aw[n];
    part[(b*8 + seg) * 128 + f] = a;
}

__global__ void pool_fin(const float* __restrict__ part, float* __restrict__ e) {
    int b = blockIdx.x, t = threadIdx.x;
    float a = 0.f;
    #pragma unroll
    for (int s = 0; s < 8; s++) a += part[(b*8 + s) * 128 + t];
    e[b * 128 + t] = a;
}

// ------------------------------------------------------------------ final scoring
__global__ void final_kernel(const float* __restrict__ e, const float* __restrict__ tn_w,
                             const float* __restrict__ tn_wb, const float* __restrict__ tn_bias,
                             const float* __restrict__ fc1_w, const float* __restrict__ fc1_b,
                             const float* __restrict__ sc_w, const float* __restrict__ sc_b,
                             float* __restrict__ out) {
    __shared__ float e1s[128], e2s[128], red[128], ts[16], hs[16];
    int b = blockIdx.x, tid = threadIdx.x;
    e1s[tid] = e[b * 128 + tid];
    e2s[tid] = e[(b + 8) * 128 + tid];
    __syncthreads();
    for (int tt = 0; tt < 16; tt++) {
        float inner = 0.f;
        const float* wrow = tn_w + (long)tid * 128 * 16 + tt;
        for (int gI = 0; gI < 128; gI++) inner += wrow[gI * 16] * e2s[gI];
        red[tid] = e1s[tid] * inner;
        __syncthreads();
        for (int s2 = 64; s2; s2 >>= 1) {
            if (tid < s2) red[tid] += red[tid + s2];
            __syncthreads();
        }
        if (tid == 0) ts[tt] = red[0];
        __syncthreads();
    }
    if (tid < 16) {
        float blk = 0.f;
        for (int c = 0; c < 128; c++) blk += tn_wb[tid * 256 + c] * e1s[c];
        for (int c = 0; c < 128; c++) blk += tn_wb[tid * 256 + 128 + c] * e2s[c];
        float v = ts[tid] + blk + tn_bias[tid];
        ts[tid] = v > 0.f ? v : 0.f;
    }
    __syncthreads();
    if (tid < 16) {
        float h = fc1_b[tid];
        for (int u2 = 0; u2 < 16; u2++) h += fc1_w[tid * 16 + u2] * ts[u2];
        hs[tid] = h > 0.f ? h : 0.f;
    }
    __syncthreads();
    if (tid == 0) {
        float z = sc_b[0];
        for (int u2 = 0; u2 < 16; u2++) z += sc_w[u2] * hs[u2];
        out[b] = 1.0f / (1.0f + expf(-z));
    }
}

// ------------------------------------------------------------------ host
template <typename T>
static float* symaddr(T& sym_) {
    void* p = nullptr;
    cudaGetSymbolAddress(&p, sym_);
    return (float*)p;
}

extern "C" void kernel_launch(void* const* d_in, const int* in_sizes, int n_in,
                              void* d_out, int out_size) {
    (void)in_sizes; (void)n_in; (void)out_size;
    const float* f1    = (const float*)d_in[0];
    const float* f2    = (const float*)d_in[1];
    const float* sw1   = (const float*)d_in[2];
    const float* sg1   = (const float*)d_in[3];
    const float* sb1   = (const float*)d_in[4];
    const float* fw1   = (const float*)d_in[5];
    const float* fg1   = (const float*)d_in[6];
    const float* fb1   = (const float*)d_in[7];
    const float* sw2   = (const float*)d_in[8];
    const float* sg2   = (const float*)d_in[9];
    const float* sb2   = (const float*)d_in[10];
    const float* fw2   = (const float*)d_in[11];
    const float* fg2   = (const float*)d_in[12];
    const float* fb2   = (const float*)d_in[13];
    const float* sw3   = (const float*)d_in[14];
    const float* sg3   = (const float*)d_in[15];
    const float* sb3   = (const float*)d_in[16];
    const float* fw3   = (const float*)d_in[17];
    const float* fg3   = (const float*)d_in[18];
    const float* fb3   = (const float*)d_in[19];
    const float* ew    = (const float*)d_in[20];
    const float* eg    = (const float*)d_in[21];
    const float* ebv   = (const float*)d_in[22];
    const float* att_w = (const float*)d_in[23];
    const float* tn_w  = (const float*)d_in[24];
    const float* tn_wb = (const float*)d_in[25];
    const float* tn_b  = (const float*)d_in[26];
    const float* fc1_w = (const float*)d_in[27];
    const float* fc1_b = (const float*)d_in[28];
    const float* sc_w  = (const float*)d_in[29];
    const float* sc_b  = (const float*)d_in[30];
    float* out = (float*)d_out;

    unsigned* negp = (unsigned*)symaddr(g_neg);
    int*   idxp  = (int*)symaddr(g_idx);
    float* xxp   = symaddr(g_xx);
    float* x0p   = symaddr(g_x0);
    float* s0p   = symaddr(g_s0);
    float* hAp   = symaddr(g_hA);
    float* hBp   = symaddr(g_hB);
    float* h3p   = symaddr(g_h3);
    float* embp  = symaddr(g_emb);
    float* partp = symaddr(g_part);
    float* gcp   = symaddr(g_gc);
    float* ep    = symaddr(g_e);

    const int SM_C1 = (2*64*6    + 8*21*8 ) * 4 + 8*KNN*4;    // conv<3,4,64,8,256,1>
    const int SM_C2 = (2*64*66   + 8*21*68) * 4 + 8*KNN*4;    // conv<64,64,64,8,256,1>
    const int SM_C3 = (2*128*66  + 8*21*68) * 4 + 8*KNN*4;    // conv<64,64,128,8,512,1>
    const int SM_C4 = (2*64*130  + 16*21*68) * 4 + 16*KNN*4;  // conv<128,128,64,16,512,2>
    const int SM_EW = (256*128 + 4*256) * 4;

    cudaFuncSetAttribute(conv_kernel<64,64,64,8,256,1>,    cudaFuncAttributeMaxDynamicSharedMemorySize, SM_C2);
    cudaFuncSetAttribute(conv_kernel<64,64,128,8,512,1>,   cudaFuncAttributeMaxDynamicSharedMemorySize, SM_C3);
    cudaFuncSetAttribute(conv_kernel<128,128,64,16,512,2>, cudaFuncAttributeMaxDynamicSharedMemorySize, SM_C4);
    cudaFuncSetAttribute(emb_kernel,                       cudaFuncAttributeMaxDynamicSharedMemorySize, SM_EW);

    static cudaStream_t sB = 0;
    static cudaEvent_t evFork = 0, evJoin = 0;
    if (!sB) {
        cudaStreamCreateWithFlags(&sB, cudaStreamNonBlocking);
        cudaEventCreateWithFlags(&evFork, cudaEventDisableTiming);
        cudaEventCreateWithFlags(&evJoin, cudaEventDisableTiming);
    }

    // transposes: xyz (tiny) then sem (tiled); both on stream 0 before fork
    transposeX_kernel<<<(NB*3*NPT + 255) / 256, 256>>>(f1, f2, x0p);
    transposeS_kernel<<<dim3(NPT/32, 4, NB), dim3(32, 8)>>>(f1, f2, s0p);
    cudaEventRecord(evFork, 0);
    cudaStreamWaitEvent(sB, evFork, 0);

    // ---- layer 1: xyz fused KNN on stream 0, sem chain on stream sB (parallel) ----
    knn4_kernel<<<NROW/16, 512>>>(x0p, idxp);
    conv_kernel<3,4,64,8,256,1><<<NB*NPT/8, 256, SM_C1>>>(x0p, idxp, sw1, sw1, sg1, sg1, sb1, sb1, hAp);

    xx_kernel<128,NROW><<<NROW/256, 256, 0, sB>>>(s0p, xxp + NROW);
    dist_kernel<128><<<dim3(8,8,NB), 256, 0, sB>>>(s0p, xxp + NROW, negp + (size_t)NROW*NPT);
    topk_kernel<<<NROW/8, 256, 0, sB>>>(negp + (size_t)NROW*NPT, idxp + NROW*KNN);
    conv_kernel<128,128,64,16,512,2><<<NB*NPT/16, 512, SM_C4, sB>>>(s0p, idxp + NROW*KNN, fw1, fw1, fg1, fg1, fb1, fb1, hAp + NROW*64);

    cudaEventRecord(evJoin, sB);
    cudaStreamWaitEvent(0, evJoin, 0);

    // ---- layer 2 (merged NB2, 64 -> 64) ----
    xx_kernel<64,NROW2><<<NROW2/256, 256>>>(hAp, xxp);
    dist_kernel<64><<<dim3(8,8,NB2), 256>>>(hAp, xxp, negp);
    topk_kernel<<<NROW2/8, 256>>>(negp, idxp);
    conv_kernel<64,64,64,8,256,1><<<NB2*NPT/8, 256, SM_C2>>>(hAp, idxp, sw2, fw2, sg2, fg2, sb2, fb2, hBp);

    // ---- layer 3 (merged NB2, 64 -> 128) ----
    xx_kernel<64,NROW2><<<NROW2/256, 256>>>(hBp, xxp);
    dist_kernel<64><<<dim3(8,8,NB2), 256>>>(hBp, xxp, negp);
    topk_kernel<<<NROW2/8, 256>>>(negp, idxp);
    conv_kernel<64,64,128,8,512,1><<<NB2*NPT/8, 512, SM_C3>>>(hBp, idxp, sw3, fw3, sg3, fg3, sb3, fb3, h3p);

    // ---- fuse + attention (all 16 batches) ----
    emb_kernel<<<NROW/32, 128, SM_EW>>>(h3p, h3p + NROW*128, ew, eg, ebv, embp);

    float* att_out = out + 8;                       // att1 (b 0..7) then att2 (b 8..15), contiguous
    gcfused_kernel<<<NB, 1024>>>(embp, att_w, gcp);
    sc_kernel<<<NROW/4, 128>>>(embp, gcp, att_out);
    pool_part<<<dim3(NB, 8), 128>>>(embp, att_out, partp);
    pool_fin<<<NB, 128>>>(partp, ep);

    final_kernel<<<BB, 128>>>(ep, tn_w, tn_wb, tn_b, fc1_w, fc1_b, sc_w, sc_b, out);
}

// round 15
// speedup vs baseline: 1.0861x; 1.0461x over previous
#include <cuda_runtime.h>
#include <math.h>
#include <stdint.h>

#define BB   8
#define NB   16          // batches per graph-pair set
#define NB2  32          // both chains merged (xyz batches 0-15, sem 16-31)
#define NPT  1024
#define KNN  20
#define NROW (NB*NPT)    // 16384
#define NROW2 (NB2*NPT)  // 32768

// ------------------------------------------------------------------ packed fp32x2 helpers
__device__ __forceinline__ void ffma2(unsigned long long& d, unsigned long long a, unsigned long long b) {
    asm("fma.rn.f32x2 %0, %1, %2, %0;" : "+l"(d) : "l"(a), "l"(b));
}
__device__ __forceinline__ unsigned long long dup2(float x) {
    unsigned long long r;
    asm("mov.b64 %0, {%1, %1};" : "=l"(r) : "f"(x));
    return r;
}
__device__ __forceinline__ float2 unpk2(unsigned long long v) {
    float2 r;
    asm("mov.b64 {%0, %1}, %2;" : "=f"(r.x), "=f"(r.y) : "l"(v));
    return r;
}
__device__ __forceinline__ unsigned mapkey(float v) {
    unsigned u = __float_as_uint(v);
    return (u & 0x80000000u) ? ~u : (u | 0x80000000u);   // order-preserving; real keys > 0
}

// ------------------------------------------------------------------ scratch
__device__ unsigned g_neg[(size_t)NROW2*NPT];   // mapped-key distance matrix
__device__ int   g_idx[NROW2*KNN];
__device__ float g_x0 [NROW*4];
__device__ float g_s0 [NROW*128];
__device__ float g_hA [NROW2*64];
__device__ float g_hB [NROW2*64];
__device__ float g_h3 [NROW2*128];     // layer-3 out: xyz half then sem half
__device__ float g_emb[NROW*128];
__device__ float g_part[NB*8*128];
__device__ float g_gc  [NB*128];
__device__ float g_e   [NB*128];

// ------------------------------------------------------------------ transposes
__global__ void transposeX_kernel(const float* __restrict__ f1, const float* __restrict__ f2,
                                  float* __restrict__ x0) {
    int j = blockIdx.x * blockDim.x + threadIdx.x;     // over NB*3*NPT
    if (j >= NB * 3 * NPT) return;
    int n = j % NPT;
    int c = (j / NPT) % 3;
    int b = j / (3 * NPT);
    const float* in = (b < BB) ? f1 : f2;
    float v = in[((long)(b & 7) * 131 + c) * NPT + n];
    x0[(b*NPT + n)*4 + c] = v;
    if (c == 0) x0[(b*NPT + n)*4 + 3] = 0.0f;
}
__global__ void transposeS_kernel(const float* __restrict__ f1, const float* __restrict__ f2,
                                  float* __restrict__ s0) {
    __shared__ float tile[32][33];
    int b  = blockIdx.z;
    int c0 = blockIdx.y * 32;
    int n0 = blockIdx.x * 32;
    const float* in = (b < BB) ? f1 : f2;
    int tx = threadIdx.x, ty = threadIdx.y;   // 32 x 8
    #pragma unroll
    for (int i = 0; i < 32; i += 8)
        tile[ty + i][tx] = in[((long)(b & 7) * 131 + 3 + c0 + ty + i) * NPT + n0 + tx];
    __syncthreads();
    #pragma unroll
    for (int i = 0; i < 32; i += 8)
        s0[((long)(b*NPT) + n0 + ty + i) * 128 + c0 + tx] = tile[tx][ty + i];
}

// ------------------------------------------------------------------ fused KNN for C=4 (xyz layer 1)
__global__ __launch_bounds__(512) void knn4_kernel(const float* __restrict__ X, int* __restrict__ idxout) {
    __shared__ float4 pts[NPT];
    __shared__ float xxc[NPT];
    int t = threadIdx.x;
    int warp = t >> 5, lane = t & 31;
    int b  = blockIdx.x / (NPT / 16);
    int r0 = (blockIdx.x % (NPT / 16)) * 16;
    const float4* Xb = (const float4*)(X + (long)b * NPT * 4);
    for (int i = t; i < NPT; i += 512) {
        float4 p = Xb[i];
        pts[i] = p;
        float a = 0.f;
        a = fmaf(p.x, p.x, a); a = fmaf(p.y, p.y, a);
        a = fmaf(p.z, p.z, a); a = fmaf(p.w, p.w, a);
        xxc[i] = a;
    }
    __syncthreads();
    long rowg = (long)(b * NPT) + r0 + warp;
    float4 rv = pts[r0 + warp];
    float xxr = xxc[r0 + warp];

    unsigned key[32];
    #pragma unroll
    for (int j = 0; j < 32; j++) {
        int col = lane + 32 * j;
        float4 pv = pts[col];
        float acc = 0.f;
        acc = fmaf(rv.x, pv.x, acc); acc = fmaf(rv.y, pv.y, acc);
        acc = fmaf(rv.z, pv.z, acc); acc = fmaf(rv.w, pv.w, acc);
        key[j] = mapkey(2.f * acc - xxr - xxc[col]);
    }

    unsigned ck0=0,ck1=0,ck2=0,ck3=0;
    unsigned ci0=0,ci1=0,ci2=0,ci3=0;
    #pragma unroll
    for (int j = 0; j < 32; j++) {
        unsigned k = key[j];
        unsigned gi = (unsigned)(lane + 32*j);
        if (k > ck3) {
            if (k > ck0)      { ck3=ck2;ci3=ci2; ck2=ck1;ci2=ci1; ck1=ck0;ci1=ci0; ck0=k;ci0=gi; }
            else if (k > ck1) { ck3=ck2;ci3=ci2; ck2=ck1;ci2=ci1; ck1=k;ci1=gi; }
            else if (k > ck2) { ck3=ck2;ci3=ci2; ck2=k;ci2=gi; }
            else              { ck3=k;ci3=gi; }
        }
    }
    unsigned removed = 0u;
    int navail = 4;
    for (int sel = 0; sel < KNN; sel++) {
        unsigned maxk = __reduce_max_sync(0xffffffffu, ck0);
        unsigned cand = (ck0 == maxk) ? ci0 : 0xffffffffu;
        unsigned widx = __reduce_min_sync(0xffffffffu, cand);
        if (lane == 0) idxout[rowg*KNN + sel] = (int)widx;
        if (ck0 == maxk && ci0 == widx) {
            removed |= 1u << (widx >> 5);
            ck0=ck1;ci0=ci1; ck1=ck2;ci1=ci2; ck2=ck3;ci2=ci3; ck3=0;ci3=0;
            if (--navail == 0) {
                ck0=ck1=ck2=ck3=0; ci0=ci1=ci2=ci3=0;
                #pragma unroll
                for (int j = 0; j < 32; j++) {
                    if ((removed >> j) & 1u) continue;
                    unsigned k = key[j];
                    unsigned gi = (unsigned)(lane + 32*j);
                    if (k > ck3) {
                        if (k > ck0)      { ck3=ck2;ci3=ci2; ck2=ck1;ci2=ci1; ck1=ck0;ci1=ci0; ck0=k;ci0=gi; }
                        else if (k > ck1) { ck3=ck2;ci3=ci2; ck2=ck1;ci2=ci1; ck1=k;ci1=gi; }
                        else if (k > ck2) { ck3=ck2;ci3=ci2; ck2=k;ci2=gi; }
                        else              { ck3=k;ci3=gi; }
                    }
                }
                navail = 4;
            }
        }
    }
}

// ------------------------------------------------------------------ neg distance -> mapped u32 keys, with FUSED row/col norms
// norm accumulation replicates xx_kernel's parity-chain order exactly (acc index = global c % 4).
template <int CROW>
__global__ __launch_bounds__(256, 1) void dist_kernel(const float* __restrict__ X,
                                                      unsigned* __restrict__ neg) {
    constexpr int TC = 16;
    constexpr int LDW = 132;
    __shared__ float As[TC][LDW];
    __shared__ float Bs[TC][LDW];
    __shared__ float xnA[128], xnB[128];
    int b = blockIdx.z;
    int row0 = blockIdx.y * 128;
    int col0 = blockIdx.x * 128;
    int t = threadIdx.x;
    int tx = t & 15, ty = t >> 4;
    int nr = t & 127;
    bool isB = t >= 128;
    float na0 = 0.f, na1 = 0.f, na2 = 0.f, na3 = 0.f;
    unsigned long long acc2[8][4];
    #pragma unroll
    for (int i = 0; i < 8; i++)
        #pragma unroll
        for (int j = 0; j < 4; j++) acc2[i][j] = 0ull;

    for (int c0 = 0; c0 < CROW; c0 += TC) {
        constexpr int NLD = (128 * TC) / 256;
        #pragma unroll
        for (int l = 0; l < NLD; l++) {
            int i = t + l * 256;
            int r = i / TC, c = i % TC;
            As[c][r] = X[((long)(b*NPT) + row0 + r) * CROW + c0 + c];
            Bs[c][r] = X[((long)(b*NPT) + col0 + r) * CROW + c0 + c];
        }
        __syncthreads();
        // fused norm accumulation (thread-per-row; parity chains match xx order)
        {
            const float (*T)[LDW] = isB ? Bs : As;
            #pragma unroll
            for (int cl = 0; cl < TC; cl += 4) {
                float v0 = T[cl+0][nr], v1 = T[cl+1][nr];
                float v2 = T[cl+2][nr], v3 = T[cl+3][nr];
                na0 = fmaf(v0, v0, na0); na1 = fmaf(v1, v1, na1);
                na2 = fmaf(v2, v2, na2); na3 = fmaf(v3, v3, na3);
            }
        }
        #pragma unroll
        for (int c = 0; c < TC; c++) {
            float4 a0 = *(const float4*)&As[c][ty*8];
            float4 a1 = *(const float4*)&As[c][ty*8+4];
            ulonglong2 b01 = *(const ulonglong2*)&Bs[c][tx*8];
            ulonglong2 b23 = *(const ulonglong2*)&Bs[c][tx*8+4];
            unsigned long long bp[4] = {b01.x, b01.y, b23.x, b23.y};
            unsigned long long ap[8];
            ap[0]=dup2(a0.x); ap[1]=dup2(a0.y); ap[2]=dup2(a0.z); ap[3]=dup2(a0.w);
            ap[4]=dup2(a1.x); ap[5]=dup2(a1.y); ap[6]=dup2(a1.z); ap[7]=dup2(a1.w);
            #pragma unroll
            for (int i = 0; i < 8; i++)
                #pragma unroll
                for (int j = 0; j < 4; j++) ffma2(acc2[i][j], ap[i], bp[j]);
        }
        __syncthreads();
    }
    if (!isB) xnA[nr] = (na0 + na1) + (na2 + na3);
    else      xnB[nr] = (na0 + na1) + (na2 + na3);
    __syncthreads();

    float xr[8], xc[8];
    #pragma unroll
    for (int i = 0; i < 8; i++) {
        xr[i] = xnA[ty*8 + i];
        xc[i] = xnB[tx*8 + i];
    }
    #pragma unroll
    for (int i = 0; i < 8; i++) {
        long rbase = ((long)(b*NPT) + row0 + ty*8 + i) * NPT + col0 + tx*8;
        float2 p0 = unpk2(acc2[i][0]);
        float2 p1 = unpk2(acc2[i][1]);
        float2 p2 = unpk2(acc2[i][2]);
        float2 p3 = unpk2(acc2[i][3]);
        uint4 o0, o1;
        o0.x = mapkey(2.f*p0.x - xr[i] - xc[0]);
        o0.y = mapkey(2.f*p0.y - xr[i] - xc[1]);
        o0.z = mapkey(2.f*p1.x - xr[i] - xc[2]);
        o0.w = mapkey(2.f*p1.y - xr[i] - xc[3]);
        o1.x = mapkey(2.f*p2.x - xr[i] - xc[4]);
        o1.y = mapkey(2.f*p2.y - xr[i] - xc[5]);
        o1.z = mapkey(2.f*p3.x - xr[i] - xc[6]);
        o1.w = mapkey(2.f*p3.y - xr[i] - xc[7]);
        *(uint4*)&neg[rbase]     = o0;
        *(uint4*)&neg[rbase + 4] = o1;
    }
}

// ------------------------------------------------------------------ top-20: warp per row, REDUX argmax + per-lane top-4 cache
__global__ __launch_bounds__(256) void topk_kernel(const unsigned* __restrict__ neg, int* __restrict__ idxout) {
    int warp = threadIdx.x >> 5, lane = threadIdx.x & 31;
    long row = (long)blockIdx.x * 8 + warp;
    const unsigned* rp = neg + row * NPT;

    unsigned ck0=0,ck1=0,ck2=0,ck3=0;
    unsigned ci0=0,ci1=0,ci2=0,ci3=0;
    #pragma unroll
    for (int g = 0; g < 8; g++) {
        uint4 kv = *(const uint4*)&rp[g*128 + lane*4];
        unsigned kk[4] = {kv.x, kv.y, kv.z, kv.w};
        #pragma unroll
        for (int q = 0; q < 4; q++) {
            unsigned k = kk[q];
            unsigned gi = (unsigned)(g*128 + lane*4 + q);
            if (k > ck3) {
                if (k > ck0)      { ck3=ck2;ci3=ci2; ck2=ck1;ci2=ci1; ck1=ck0;ci1=ci0; ck0=k;ci0=gi; }
                else if (k > ck1) { ck3=ck2;ci3=ci2; ck2=ck1;ci2=ci1; ck1=k;ci1=gi; }
                else if (k > ck2) { ck3=ck2;ci3=ci2; ck2=k;ci2=gi; }
                else              { ck3=k;ci3=gi; }
            }
        }
    }
    unsigned removed = 0u;   // bit j = 4*g + q
    int navail = 4;
    for (int sel = 0; sel < KNN; sel++) {
        unsigned maxk = __reduce_max_sync(0xffffffffu, ck0);
        unsigned cand = (ck0 == maxk) ? ci0 : 0xffffffffu;
        unsigned widx = __reduce_min_sync(0xffffffffu, cand);
        if (lane == 0) idxout[row*KNN + sel] = (int)widx;
        if (ck0 == maxk && ci0 == widx) {
            int jw = (int)(((widx >> 7) << 2) | (widx & 3u));
            removed |= 1u << jw;
            ck0=ck1;ci0=ci1; ck1=ck2;ci1=ci2; ck2=ck3;ci2=ci3; ck3=0;ci3=0;
            if (--navail == 0) {
                ck0=ck1=ck2=ck3=0; ci0=ci1=ci2=ci3=0;
                for (int g = 0; g < 8; g++) {
                    uint4 kv = *(const uint4*)&rp[g*128 + lane*4];
                    unsigned kk[4] = {kv.x, kv.y, kv.z, kv.w};
                    #pragma unroll
                    for (int q = 0; q < 4; q++) {
                        if ((removed >> (4*g + q)) & 1u) continue;
                        unsigned k = kk[q];
                        unsigned gi = (unsigned)(g*128 + lane*4 + q);
                        if (k > ck3) {
                            if (k > ck0)      { ck3=ck2;ci3=ci2; ck2=ck1;ci2=ci1; ck1=ck0;ci1=ci0; ck0=k;ci0=gi; }
                            else if (k > ck1) { ck3=ck2;ci3=ci2; ck2=ck1;ci2=ci1; ck1=k;ci1=gi; }
                            else if (k > ck2) { ck3=ck2;ci3=ci2; ck2=k;ci2=gi; }
                            else              { ck3=k;ci3=gi; }
                        }
                    }
                }
                navail = 4;
            }
        }
    }
}

// ------------------------------------------------------------------ conv layer-1 xyz specialized (CIN=3, scalar accumulators, no padded channel)
__global__ __launch_bounds__(512) void conv1_kernel(const float* __restrict__ X, const int* __restrict__ idx,
                                                    const float* __restrict__ w, const float* __restrict__ gam,
                                                    const float* __restrict__ bet, float* __restrict__ out) {
    constexpr int WST = 6, CP = 8;
    __shared__ float w1T[64*WST], wdT[64*WST];
    __shared__ float nb[8*21*CP];
    __shared__ int sidx[8*KNN];
    int t = threadIdx.x;
    int b  = blockIdx.x >> 7;
    int n0 = (blockIdx.x & 127) * 8;

    for (int i = t; i < 64*3; i += 512) {
        int o = i / 3, c = i % 3;
        float w1 = w[o*6 + c];
        w1T[o*WST + c] = w1;
        wdT[o*WST + c] = w[o*6 + 3 + c] - w1;
    }
    for (int i = t; i < 8*KNN; i += 512)
        sidx[i] = idx[((long)(b*NPT) + n0) * KNN + i];
    __syncthreads();
    for (int i = t; i < 8*21; i += 512) {
        int p = i / 21, k = i % 21;
        int m = (k < KNN) ? sidx[p*KNN + k] : (n0 + p);
        *(float4*)&nb[i*CP] = *(const float4*)&X[((long)(b*NPT) + m) * 4];
    }
    __syncthreads();

    int p = t >> 6, o = t & 63;
    const float* nbp = &nb[p*21*CP];
    float s[KNN];
    float u = 0.f;
    #pragma unroll
    for (int k = 0; k < KNN; k++) s[k] = 0.f;
    #pragma unroll
    for (int c = 0; c < 3; c++) {
        float w1 = w1T[o*WST + c];
        float wd = wdT[o*WST + c];
        u = fmaf(wd, nbp[20*CP + c], u);
        #pragma unroll
        for (int k = 0; k < KNN; k++)
            s[k] = fmaf(w1, nbp[k*CP + c], s[k]);
    }
    float mx = s[0], mn = s[0];
    #pragma unroll
    for (int k = 1; k < KNN; k++) { mx = fmaxf(mx, s[k]); mn = fminf(mn, s[k]); }
    float inv = rsqrtf(1.0f + 1e-5f);
    float g = gam[o], bt = bet[o];
    float aa = g * inv;
    float base = ((aa >= 0.f) ? mx : mn) + u;
    float v = aa * base + bt;
    out[((long)(b*NPT) + n0 + p) * 64 + o] = v >= 0.f ? v : 0.2f * v;
}

// ------------------------------------------------------------------ fused gather + edge conv + BN + leaky + max_k  (c-paired FFMA2)
template <int CIN, int CROW, int COUT, int P, int THREADS, int NPH>
__global__ __launch_bounds__(THREADS, 1)
void conv_kernel(const float* __restrict__ X, const int* __restrict__ idx,
                 const float* __restrict__ w_a, const float* __restrict__ w_b,
                 const float* __restrict__ gam_a, const float* __restrict__ gam_b,
                 const float* __restrict__ bet_a, const float* __restrict__ bet_b,
                 float* __restrict__ out) {
    constexpr int TPP = THREADS / P;
    static_assert(TPP == COUT / 2, "CPT must be 2");
    constexpr int CPH = CROW / NPH;
    constexpr int WST = CROW + 2;
    constexpr int CP  = CPH + 4;
    extern __shared__ float sm[];
    float* w1T = sm;
    float* wdT = w1T + COUT * WST;
    float* nb  = wdT + COUT * WST;
    int* sidx  = (int*)(nb + P * 21 * CP);

    int t = threadIdx.x;
    int b  = blockIdx.x / (NPT / P);
    int n0 = (blockIdx.x % (NPT / P)) * P;
    const float* w   = (b < NB) ? w_a : w_b;
    const float* gam = (b < NB) ? gam_a : gam_b;
    const float* bet = (b < NB) ? bet_a : bet_b;

    for (int i = t; i < COUT * CROW; i += THREADS) {
        int o = i / CROW, c = i % CROW;
        float w1 = (c < CIN) ? w[o * (2*CIN) + c] : 0.f;
        float w2 = (c < CIN) ? w[o * (2*CIN) + CIN + c] : 0.f;
        w1T[o * WST + c] = w1;
        wdT[o * WST + c] = w2 - w1;
    }
    for (int i = t; i < P * KNN; i += THREADS)
        sidx[i] = idx[((long)(b*NPT) + n0) * KNN + i];
    __syncthreads();

    int p  = t / TPP;
    int o0 = t % TPP;
    int o1 = o0 + COUT / 2;
    unsigned long long s0[KNN], s1[KNN];
    unsigned long long u0 = 0ull, u1 = 0ull;
    #pragma unroll
    for (int k = 0; k < KNN; k++) { s0[k] = 0ull; s1[k] = 0ull; }

    const float* nbp = nb + p * 21 * CP;
    constexpr int V4 = CPH / 4;
    for (int ph = 0; ph < NPH; ph++) {
        if (ph > 0) __syncthreads();
        for (int i = t; i < P * 21 * V4; i += THREADS) {
            int c4 = i % V4;
            int vec = i / V4;
            int pp = vec / 21, k = vec % 21;
            int m = (k < KNN) ? sidx[pp*KNN + k] : (n0 + pp);
            float4 v = *(const float4*)&X[((long)(b*NPT) + m) * CROW + ph*CPH + 4*c4];
            *(float4*)&nb[(pp*21 + k) * CP + 4*c4] = v;
        }
        __syncthreads();

        #pragma unroll 1
        for (int c2 = 0; c2 < CPH/2; c2++) {
            int cl = 2 * c2;
            int cg = ph * CPH + cl;
            unsigned long long w1p0 = *(const unsigned long long*)&w1T[o0 * WST + cg];
            unsigned long long w1p1 = *(const unsigned long long*)&w1T[o1 * WST + cg];
            unsigned long long wdp0 = *(const unsigned long long*)&wdT[o0 * WST + cg];
            unsigned long long wdp1 = *(const unsigned long long*)&wdT[o1 * WST + cg];
            unsigned long long ctr = *(const unsigned long long*)&nbp[20 * CP + cl];
            ffma2(u0, wdp0, ctr);
            ffma2(u1, wdp1, ctr);
            #pragma unroll
            for (int k = 0; k < KNN; k++) {
                unsigned long long nbk = *(const unsigned long long*)&nbp[k * CP + cl];
                ffma2(s0[k], w1p0, nbk);
                ffma2(s1[k], w1p1, nbk);
            }
        }
    }

    float inv = rsqrtf(1.0f + 1e-5f);
    int n = n0 + p;
    float* op = &out[((long)(b*NPT) + n) * COUT];
    {
        float2 h = unpk2(s0[0]);
        float v0 = h.x + h.y;
        float mx = v0, mn = v0;
        #pragma unroll
        for (int k = 1; k < KNN; k++) {
            float2 hk = unpk2(s0[k]);
            float vk = hk.x + hk.y;
            mx = fmaxf(mx, vk); mn = fminf(mn, vk);
        }
        float2 up = unpk2(u0);
        float uu = up.x + up.y;
        float g = gam[o0], bt = bet[o0];
        float aa = g * inv;
        float base = ((aa >= 0.f) ? mx : mn) + uu;
        float v = aa * base + bt;
        op[o0] = v >= 0.f ? v : 0.2f * v;
    }
    {
        float2 h = unpk2(s1[0]);
        float v0 = h.x + h.y;
        float mx = v0, mn = v0;
        #pragma unroll
        for (int k = 1; k < KNN; k++) {
            float2 hk = unpk2(s1[k]);
            float vk = hk.x + hk.y;
            mx = fmaxf(mx, vk); mn = fminf(mn, vk);
        }
        float2 up = unpk2(u1);
        float uu = up.x + up.y;
        float g = gam[o1], bt = bet[o1];
        float aa = g * inv;
        float base = ((aa >= 0.f) ? mx : mn) + uu;
        float v = aa * base + bt;
        op[o1] = v >= 0.f ? v : 0.2f * v;
    }
}

// ------------------------------------------------------------------ ew conv on concat(H3,S3) -> emb (packed FMA, 8 points in flight)
__global__ __launch_bounds__(256)
void emb_kernel(const float* __restrict__ H3, const float* __restrict__ S3,
                const float* __restrict__ ew, const float* __restrict__ eg,
                const float* __restrict__ eb, float* __restrict__ emb) {
    extern __shared__ float sm[];
    float* wts  = sm;                 // [256][128]
    float* rows = wts + 256 * 128;    // [8][256]
    int t = threadIdx.x;
    for (int i = t; i < 256 * 128; i += 256) {
        int c = i / 128, o = i % 128;
        wts[c * 128 + o] = ew[o * 256 + c];
    }
    const int NITER = 16;
    int base = blockIdx.x * (8 * NITER);
    int pl = t >> 5;                  // 0..7
    int o4 = (t & 31) * 4;
    float inv = rsqrtf(1.0f + 1e-5f);
    for (int it = 0; it < NITER; it++) {
        __syncthreads();
        int p0 = base + it * 8;
        for (int i = t; i < 8 * 256; i += 256) {
            int pp = i / 256, c = i % 256;
            long pt = p0 + pp;
            rows[pp * 256 + c] = (c < 128) ? H3[pt * 128 + c] : S3[pt * 128 + c - 128];
        }
        __syncthreads();
        unsigned long long acc2[2] = {0ull, 0ull};
        for (int c = 0; c < 256; c++) {
            ulonglong2 wp = *(const ulonglong2*)&wts[c * 128 + o4];
            unsigned long long xd = dup2(rows[pl * 256 + c]);
            ffma2(acc2[0], wp.x, xd);
            ffma2(acc2[1], wp.y, xd);
        }
        float2 axy = unpk2(acc2[0]);
        float2 azw = unpk2(acc2[1]);
        float4 gmv = *(const float4*)&eg[o4];
        float4 btv = *(const float4*)&eb[o4];
        float4 r;
        { float v = gmv.x*inv*axy.x + btv.x; r.x = v>=0.f?v:0.2f*v; }
        { float v = gmv.y*inv*axy.y + btv.y; r.y = v>=0.f?v:0.2f*v; }
        { float v = gmv.z*inv*azw.x + btv.z; r.z = v>=0.f?v:0.2f*v; }
        { float v = gmv.w*inv*azw.y + btv.w; r.w = v>=0.f?v:0.2f*v; }
        long pt = p0 + pl;
        *(float4*)&emb[pt * 128 + o4] = r;
    }
}

// ------------------------------------------------------------------ attention pieces
__global__ void gcfused_kernel(const float* __restrict__ emb, const float* __restrict__ att_w,
                               float* __restrict__ gc) {
    __shared__ float part[8][128];
    __shared__ float es[128];
    int b = blockIdx.x, t = threadIdx.x;      // 1024 threads
    int seg = t >> 7, f = t & 127;
    const float* p = emb + ((long)(b*NPT) + seg*128) * 128 + f;
    float a = 0.f;
    #pragma unroll 4
    for (int n = 0; n < 128; n++) a += p[n * 128];
    part[seg][f] = a;
    __syncthreads();
    if (t < 128) {
        float s = 0.f;
        #pragma unroll
        for (int s8 = 0; s8 < 8; s8++) s += part[s8][t];
        es[t] = s;
    }
    __syncthreads();
    if (t < 128) {
        float gv = 0.f;
        for (int f2 = 0; f2 < 128; f2++) gv += es[f2] * att_w[f2 * 128 + t];
        gc[b * 128 + t] = tanhf(gv * (1.0f / NPT));
    }
}

__global__ void sc_kernel(const float* __restrict__ emb, const float* __restrict__ gc,
                          float* __restrict__ att) {
    int warp = threadIdx.x >> 5, lane = threadIdx.x & 31;
    int pid = blockIdx.x * 4 + warp;
    int b = pid >> 10;
    float a = 0.f;
    #pragma unroll
    for (int j = 0; j < 4; j++) {
        int f = lane + 32 * j;
        a += emb[(long)pid * 128 + f] * gc[b * 128 + f];
    }
    #pragma unroll
    for (int off = 16; off; off >>= 1) a += __shfl_down_sync(0xffffffffu, a, off);
    if (lane == 0) att[pid] = 1.0f / (1.0f + expf(-a));
}

__global__ void pool_part(const float* __restrict__ emb, const float* __restrict__ att,
                          float* __restrict__ part) {
    int b = blockIdx.x, seg = blockIdx.y, f = threadIdx.x;
    const float* p = emb + ((long)(b*NPT) + seg*128) * 128 + f;
    const float* aw = att + b*NPT + seg*128;
    float a = 0.f;
    #pragma unroll 4
    for (int n = 0; n < 128; n++) a += p[n * 128] * aw[n];
    part[(b*8 + seg) * 128 + f] = a;
}

__global__ void pool_fin(const float* __restrict__ part, float* __restrict__ e) {
    int b = blockIdx.x, t = threadIdx.x;
    float a = 0.f;
    #pragma unroll
    for (int s = 0; s < 8; s++) a += part[(b*8 + s) * 128 + t];
    e[b * 128 + t] = a;
}

// ------------------------------------------------------------------ final scoring
__global__ void final_kernel(const float* __restrict__ e, const float* __restrict__ tn_w,
                             const float* __restrict__ tn_wb, const float* __restrict__ tn_bias,
                             const float* __restrict__ fc1_w, const float* __restrict__ fc1_b,
                             const float* __restrict__ sc_w, const float* __restrict__ sc_b,
                             float* __restrict__ out) {
    __shared__ float e1s[128], e2s[128], red[128], ts[16], hs[16];
    int b = blockIdx.x, tid = threadIdx.x;
    e1s[tid] = e[b * 128 + tid];
    e2s[tid] = e[(b + 8) * 128 + tid];
    __syncthreads();
    for (int tt = 0; tt < 16; tt++) {
        float inner = 0.f;
        const float* wrow = tn_w + (long)tid * 128 * 16 + tt;
        for (int gI = 0; gI < 128; gI++) inner += wrow[gI * 16] * e2s[gI];
        red[tid] = e1s[tid] * inner;
        __syncthreads();
        for (int s2 = 64; s2; s2 >>= 1) {
            if (tid < s2) red[tid] += red[tid + s2];
            __syncthreads();
        }
        if (tid == 0) ts[tt] = red[0];
        __syncthreads();
    }
    if (tid < 16) {
        float blk = 0.f;
        for (int c = 0; c < 128; c++) blk += tn_wb[tid * 256 + c] * e1s[c];
        for (int c = 0; c < 128; c++) blk += tn_wb[tid * 256 + 128 + c] * e2s[c];
        float v = ts[tid] + blk + tn_bias[tid];
        ts[tid] = v > 0.f ? v : 0.f;
    }
    __syncthreads();
    if (tid < 16) {
        float h = fc1_b[tid];
        for (int u2 = 0; u2 < 16; u2++) h += fc1_w[tid * 16 + u2] * ts[u2];
        hs[tid] = h > 0.f ? h : 0.f;
    }
    __syncthreads();
    if (tid == 0) {
        float z = sc_b[0];
        for (int u2 = 0; u2 < 16; u2++) z += sc_w[u2] * hs[u2];
        out[b] = 1.0f / (1.0f + expf(-z));
    }
}

// ------------------------------------------------------------------ host
template <typename T>
static float* symaddr(T& sym_) {
    void* p = nullptr;
    cudaGetSymbolAddress(&p, sym_);
    return (float*)p;
}

extern "C" void kernel_launch(void* const* d_in, const int* in_sizes, int n_in,
                              void* d_out, int out_size) {
    (void)in_sizes; (void)n_in; (void)out_size;
    const float* f1    = (const float*)d_in[0];
    const float* f2    = (const float*)d_in[1];
    const float* sw1   = (const float*)d_in[2];
    const float* sg1   = (const float*)d_in[3];
    const float* sb1   = (const float*)d_in[4];
    const float* fw1   = (const float*)d_in[5];
    const float* fg1   = (const float*)d_in[6];
    const float* fb1   = (const float*)d_in[7];
    const float* sw2   = (const float*)d_in[8];
    const float* sg2   = (const float*)d_in[9];
    const float* sb2   = (const float*)d_in[10];
    const float* fw2   = (const float*)d_in[11];
    const float* fg2   = (const float*)d_in[12];
    const float* fb2   = (const float*)d_in[13];
    const float* sw3   = (const float*)d_in[14];
    const float* sg3   = (const float*)d_in[15];
    const float* sb3   = (const float*)d_in[16];
    const float* fw3   = (const float*)d_in[17];
    const float* fg3   = (const float*)d_in[18];
    const float* fb3   = (const float*)d_in[19];
    const float* ew    = (const float*)d_in[20];
    const float* eg    = (const float*)d_in[21];
    const float* ebv   = (const float*)d_in[22];
    const float* att_w = (const float*)d_in[23];
    const float* tn_w  = (const float*)d_in[24];
    const float* tn_wb = (const float*)d_in[25];
    const float* tn_b  = (const float*)d_in[26];
    const float* fc1_w = (const float*)d_in[27];
    const float* fc1_b = (const float*)d_in[28];
    const float* sc_w  = (const float*)d_in[29];
    const float* sc_b  = (const float*)d_in[30];
    float* out = (float*)d_out;

    unsigned* negp = (unsigned*)symaddr(g_neg);
    int*   idxp  = (int*)symaddr(g_idx);
    float* x0p   = symaddr(g_x0);
    float* s0p   = symaddr(g_s0);
    float* hAp   = symaddr(g_hA);
    float* hBp   = symaddr(g_hB);
    float* h3p   = symaddr(g_h3);
    float* embp  = symaddr(g_emb);
    float* partp = symaddr(g_part);
    float* gcp   = symaddr(g_gc);
    float* ep    = symaddr(g_e);

    const int SM_C2 = (2*64*66   + 8*21*68) * 4 + 8*KNN*4;    // conv<64,64,64,8,256,1>
    const int SM_C3 = (2*128*66  + 8*21*68) * 4 + 8*KNN*4;    // conv<64,64,128,8,512,1>
    const int SM_C4 = (2*64*130  + 16*21*68) * 4 + 16*KNN*4;  // conv<128,128,64,16,512,2>
    const int SM_EW = (256*128 + 8*256) * 4;

    cudaFuncSetAttribute(conv_kernel<64,64,64,8,256,1>,    cudaFuncAttributeMaxDynamicSharedMemorySize, SM_C2);
    cudaFuncSetAttribute(conv_kernel<64,64,128,8,512,1>,   cudaFuncAttributeMaxDynamicSharedMemorySize, SM_C3);
    cudaFuncSetAttribute(conv_kernel<128,128,64,16,512,2>, cudaFuncAttributeMaxDynamicSharedMemorySize, SM_C4);
    cudaFuncSetAttribute(emb_kernel,                       cudaFuncAttributeMaxDynamicSharedMemorySize, SM_EW);

    static cudaStream_t sB = 0;
    static cudaEvent_t evFork = 0, evJoin = 0;
    if (!sB) {
        cudaStreamCreateWithFlags(&sB, cudaStreamNonBlocking);
        cudaEventCreateWithFlags(&evFork, cudaEventDisableTiming);
        cudaEventCreateWithFlags(&evJoin, cudaEventDisableTiming);
    }

    transposeX_kernel<<<(NB*3*NPT + 255) / 256, 256>>>(f1, f2, x0p);
    transposeS_kernel<<<dim3(NPT/32, 4, NB), dim3(32, 8)>>>(f1, f2, s0p);
    cudaEventRecord(evFork, 0);
    cudaStreamWaitEvent(sB, evFork, 0);

    // ---- layer 1: xyz fused KNN + conv1 on stream 0, sem chain on stream sB (parallel) ----
    knn4_kernel<<<NROW/16, 512>>>(x0p, idxp);
    conv1_kernel<<<NB*NPT/8, 512>>>(x0p, idxp, sw1, sg1, sb1, hAp);

    dist_kernel<128><<<dim3(8,8,NB), 256, 0, sB>>>(s0p, negp + (size_t)NROW*NPT);
    topk_kernel<<<NROW/8, 256, 0, sB>>>(negp + (size_t)NROW*NPT, idxp + NROW*KNN);
    conv_kernel<128,128,64,16,512,2><<<NB*NPT/16, 512, SM_C4, sB>>>(s0p, idxp + NROW*KNN, fw1, fw1, fg1, fg1, fb1, fb1, hAp + NROW*64);

    cudaEventRecord(evJoin, sB);
    cudaStreamWaitEvent(0, evJoin, 0);

    // ---- layer 2 (merged NB2, 64 -> 64) ----
    dist_kernel<64><<<dim3(8,8,NB2), 256>>>(hAp, negp);
    topk_kernel<<<NROW2/8, 256>>>(negp, idxp);
    conv_kernel<64,64,64,8,256,1><<<NB2*NPT/8, 256, SM_C2>>>(hAp, idxp, sw2, fw2, sg2, fg2, sb2, fb2, hBp);

    // ---- layer 3 (merged NB2, 64 -> 128) ----
    dist_kernel<64><<<dim3(8,8,NB2), 256>>>(hBp, negp);
    topk_kernel<<<NROW2/8, 256>>>(negp, idxp);
    conv_kernel<64,64,128,8,512,1><<<NB2*NPT/8, 512, SM_C3>>>(hBp, idxp, sw3, fw3, sg3, fg3, sb3, fb3, h3p);

    // ---- fuse + attention (all 16 batches) ----
    emb_kernel<<<NROW/128, 256, SM_EW>>>(h3p, h3p + NROW*128, ew, eg, ebv, embp);

    float* att_out = out + 8;                       // att1 (b 0..7) then att2 (b 8..15), contiguous
    gcfused_kernel<<<NB, 1024>>>(embp, att_w, gcp);
    sc_kernel<<<NROW/4, 128>>>(embp, gcp, att_out);
    pool_part<<<dim3(NB, 8), 128>>>(embp, att_out, partp);
    pool_fin<<<NB, 128>>>(partp, ep);

    final_kernel<<<BB, 128>>>(ep, tn_w, tn_wb, tn_b, fc1_w, fc1_b, sc_w, sc_b, out);
}

// round 16
// speedup vs baseline: 1.0876x; 1.0014x over previous
#include <cuda_runtime.h>
#include <math.h>
#include <stdint.h>

#define BB   8
#define NB   16          // batches per graph-pair set
#define NB2  32          // both chains merged (xyz batches 0-15, sem 16-31)
#define NPT  1024
#define KNN  20
#define NROW (NB*NPT)    // 16384
#define NROW2 (NB2*NPT)  // 32768
#define SPL  7           // sem layer-1 batches assigned to stream 0

// ------------------------------------------------------------------ packed fp32x2 helpers
__device__ __forceinline__ void ffma2(unsigned long long& d, unsigned long long a, unsigned long long b) {
    asm("fma.rn.f32x2 %0, %1, %2, %0;" : "+l"(d) : "l"(a), "l"(b));
}
__device__ __forceinline__ unsigned long long dup2(float x) {
    unsigned long long r;
    asm("mov.b64 %0, {%1, %1};" : "=l"(r) : "f"(x));
    return r;
}
__device__ __forceinline__ float2 unpk2(unsigned long long v) {
    float2 r;
    asm("mov.b64 {%0, %1}, %2;" : "=f"(r.x), "=f"(r.y) : "l"(v));
    return r;
}
__device__ __forceinline__ unsigned mapkey(float v) {
    unsigned u = __float_as_uint(v);
    return (u & 0x80000000u) ? ~u : (u | 0x80000000u);   // order-preserving; real keys > 0
}

// ------------------------------------------------------------------ scratch
__device__ unsigned g_neg[(size_t)NROW2*NPT];   // mapped-key distance matrix
__device__ int   g_idx[NROW2*KNN];
__device__ float g_x0 [NROW*4];
__device__ float g_s0 [NROW*128];
__device__ float g_hA [NROW2*64];
__device__ float g_hB [NROW2*64];
__device__ float g_h3 [NROW2*128];     // layer-3 out: xyz half then sem half
__device__ float g_emb[NROW*128];
__device__ float g_part[NB*8*128];
__device__ float g_gc  [NB*128];
__device__ float g_e   [NB*128];

// ------------------------------------------------------------------ transposes
__global__ void transposeX_kernel(const float* __restrict__ f1, const float* __restrict__ f2,
                                  float* __restrict__ x0) {
    int j = blockIdx.x * blockDim.x + threadIdx.x;     // over NB*3*NPT
    if (j >= NB * 3 * NPT) return;
    int n = j % NPT;
    int c = (j / NPT) % 3;
    int b = j / (3 * NPT);
    const float* in = (b < BB) ? f1 : f2;
    float v = in[((long)(b & 7) * 131 + c) * NPT + n];
    x0[(b*NPT + n)*4 + c] = v;
    if (c == 0) x0[(b*NPT + n)*4 + 3] = 0.0f;
}
__global__ void transposeS_kernel(const float* __restrict__ f1, const float* __restrict__ f2,
                                  float* __restrict__ s0) {
    __shared__ float tile[32][33];
    int b  = blockIdx.z;
    int c0 = blockIdx.y * 32;
    int n0 = blockIdx.x * 32;
    const float* in = (b < BB) ? f1 : f2;
    int tx = threadIdx.x, ty = threadIdx.y;   // 32 x 8
    #pragma unroll
    for (int i = 0; i < 32; i += 8)
        tile[ty + i][tx] = in[((long)(b & 7) * 131 + 3 + c0 + ty + i) * NPT + n0 + tx];
    __syncthreads();
    #pragma unroll
    for (int i = 0; i < 32; i += 8)
        s0[((long)(b*NPT) + n0 + ty + i) * 128 + c0 + tx] = tile[tx][ty + i];
}

// ------------------------------------------------------------------ fused KNN + edge conv for xyz layer 1 (C=4)
// Selection identical to knn4; conv accumulated in-loop (widx is broadcast to all lanes
// by the REDUX ops), replicating conv1's FMA chains and max-order bit-exactly.
__global__ __launch_bounds__(512) void knnconv1_kernel(const float* __restrict__ X,
                                                       const float* __restrict__ w,
                                                       const float* __restrict__ gam,
                                                       const float* __restrict__ bet,
                                                       float* __restrict__ out) {
    __shared__ float4 pts[NPT];
    __shared__ float xxc[NPT];
    __shared__ float w1s[64*4], wds[64*4];
    int t = threadIdx.x;
    int warp = t >> 5, lane = t & 31;
    int b  = blockIdx.x / (NPT / 16);
    int r0 = (blockIdx.x % (NPT / 16)) * 16;
    const float4* Xb = (const float4*)(X + (long)b * NPT * 4);
    for (int i = t; i < NPT; i += 512) {
        float4 p = pts[i] = Xb[i];
        float a = 0.f;
        a = fmaf(p.x, p.x, a); a = fmaf(p.y, p.y, a);
        a = fmaf(p.z, p.z, a); a = fmaf(p.w, p.w, a);
        xxc[i] = a;
    }
    for (int i = t; i < 64*3; i += 512) {
        int o = i / 3, c = i % 3;
        float w1 = w[o*6 + c];
        w1s[o*4 + c] = w1;
        wds[o*4 + c] = w[o*6 + 3 + c] - w1;
    }
    __syncthreads();
    long rowg = (long)(b * NPT) + r0 + warp;
    float4 rv = pts[r0 + warp];
    float xxr = xxc[r0 + warp];

    unsigned key[32];
    #pragma unroll
    for (int j = 0; j < 32; j++) {
        int col = lane + 32 * j;
        float4 pv = pts[col];
        float acc = 0.f;
        acc = fmaf(rv.x, pv.x, acc); acc = fmaf(rv.y, pv.y, acc);
        acc = fmaf(rv.z, pv.z, acc); acc = fmaf(rv.w, pv.w, acc);
        key[j] = mapkey(2.f * acc - xxr - xxc[col]);
    }

    int o0 = lane, o1 = lane + 32;
    float w10x = w1s[o0*4], w10y = w1s[o0*4+1], w10z = w1s[o0*4+2];
    float w11x = w1s[o1*4], w11y = w1s[o1*4+1], w11z = w1s[o1*4+2];
    float u0 = 0.f, u1 = 0.f;
    u0 = fmaf(wds[o0*4], rv.x, u0); u0 = fmaf(wds[o0*4+1], rv.y, u0); u0 = fmaf(wds[o0*4+2], rv.z, u0);
    u1 = fmaf(wds[o1*4], rv.x, u1); u1 = fmaf(wds[o1*4+1], rv.y, u1); u1 = fmaf(wds[o1*4+2], rv.z, u1);
    float mx0 = 0.f, mn0 = 0.f, mx1 = 0.f, mn1 = 0.f;

    unsigned ck0=0,ck1=0,ck2=0,ck3=0;
    unsigned ci0=0,ci1=0,ci2=0,ci3=0;
    #pragma unroll
    for (int j = 0; j < 32; j++) {
        unsigned k = key[j];
        unsigned gi = (unsigned)(lane + 32*j);
        if (k > ck3) {
            if (k > ck0)      { ck3=ck2;ci3=ci2; ck2=ck1;ci2=ci1; ck1=ck0;ci1=ci0; ck0=k;ci0=gi; }
            else if (k > ck1) { ck3=ck2;ci3=ci2; ck2=ck1;ci2=ci1; ck1=k;ci1=gi; }
            else if (k > ck2) { ck3=ck2;ci3=ci2; ck2=k;ci2=gi; }
            else              { ck3=k;ci3=gi; }
        }
    }
    unsigned removed = 0u;
    int navail = 4;
    for (int sel = 0; sel < KNN; sel++) {
        unsigned maxk = __reduce_max_sync(0xffffffffu, ck0);
        unsigned cand = (ck0 == maxk) ? ci0 : 0xffffffffu;
        unsigned widx = __reduce_min_sync(0xffffffffu, cand);
        // fused conv accumulation (widx broadcast; smem broadcast read)
        {
            float4 pv = pts[widx];
            float sk0 = 0.f, sk1 = 0.f;
            sk0 = fmaf(w10x, pv.x, sk0); sk0 = fmaf(w10y, pv.y, sk0); sk0 = fmaf(w10z, pv.z, sk0);
            sk1 = fmaf(w11x, pv.x, sk1); sk1 = fmaf(w11y, pv.y, sk1); sk1 = fmaf(w11z, pv.z, sk1);
            if (sel == 0) { mx0 = mn0 = sk0; mx1 = mn1 = sk1; }
            else {
                mx0 = fmaxf(mx0, sk0); mn0 = fminf(mn0, sk0);
                mx1 = fmaxf(mx1, sk1); mn1 = fminf(mn1, sk1);
            }
        }
        if (ck0 == maxk && ci0 == widx) {
            removed |= 1u << (widx >> 5);
            ck0=ck1;ci0=ci1; ck1=ck2;ci1=ci2; ck2=ck3;ci2=ci3; ck3=0;ci3=0;
            if (--navail == 0) {
                ck0=ck1=ck2=ck3=0; ci0=ci1=ci2=ci3=0;
                #pragma unroll
                for (int j = 0; j < 32; j++) {
                    if ((removed >> j) & 1u) continue;
                    unsigned k = key[j];
                    unsigned gi = (unsigned)(lane + 32*j);
                    if (k > ck3) {
                        if (k > ck0)      { ck3=ck2;ci3=ci2; ck2=ck1;ci2=ci1; ck1=ck0;ci1=ci0; ck0=k;ci0=gi; }
                        else if (k > ck1) { ck3=ck2;ci3=ci2; ck2=ck1;ci2=ci1; ck1=k;ci1=gi; }
                        else if (k > ck2) { ck3=ck2;ci3=ci2; ck2=k;ci2=gi; }
                        else              { ck3=k;ci3=gi; }
                    }
                }
                navail = 4;
            }
        }
    }
    float inv = rsqrtf(1.0f + 1e-5f);
    {
        float g = gam[o0], bt = bet[o0];
        float aa = g * inv;
        float base = ((aa >= 0.f) ? mx0 : mn0) + u0;
        float v = aa * base + bt;
        out[rowg * 64 + o0] = v >= 0.f ? v : 0.2f * v;
    }
    {
        float g = gam[o1], bt = bet[o1];
        float aa = g * inv;
        float base = ((aa >= 0.f) ? mx1 : mn1) + u1;
        float v = aa * base + bt;
        out[rowg * 64 + o1] = v >= 0.f ? v : 0.2f * v;
    }
}

// ------------------------------------------------------------------ neg distance -> mapped u32 keys, with FUSED row/col norms
template <int CROW>
__global__ __launch_bounds__(256, 1) void dist_kernel(const float* __restrict__ X,
                                                      unsigned* __restrict__ neg) {
    constexpr int TC = 16;
    constexpr int LDW = 132;
    __shared__ float As[TC][LDW];
    __shared__ float Bs[TC][LDW];
    __shared__ float xnA[128], xnB[128];
    int b = blockIdx.z;
    int row0 = blockIdx.y * 128;
    int col0 = blockIdx.x * 128;
    int t = threadIdx.x;
    int tx = t & 15, ty = t >> 4;
    int nr = t & 127;
    bool isB = t >= 128;
    float na0 = 0.f, na1 = 0.f, na2 = 0.f, na3 = 0.f;
    unsigned long long acc2[8][4];
    #pragma unroll
    for (int i = 0; i < 8; i++)
        #pragma unroll
        for (int j = 0; j < 4; j++) acc2[i][j] = 0ull;

    for (int c0 = 0; c0 < CROW; c0 += TC) {
        constexpr int NLD = (128 * TC) / 256;
        #pragma unroll
        for (int l = 0; l < NLD; l++) {
            int i = t + l * 256;
            int r = i / TC, c = i % TC;
            As[c][r] = X[((long)(b*NPT) + row0 + r) * CROW + c0 + c];
            Bs[c][r] = X[((long)(b*NPT) + col0 + r) * CROW + c0 + c];
        }
        __syncthreads();
        {
            const float (*T)[LDW] = isB ? Bs : As;
            #pragma unroll
            for (int cl = 0; cl < TC; cl += 4) {
                float v0 = T[cl+0][nr], v1 = T[cl+1][nr];
                float v2 = T[cl+2][nr], v3 = T[cl+3][nr];
                na0 = fmaf(v0, v0, na0); na1 = fmaf(v1, v1, na1);
                na2 = fmaf(v2, v2, na2); na3 = fmaf(v3, v3, na3);
            }
        }
        #pragma unroll
        for (int c = 0; c < TC; c++) {
            float4 a0 = *(const float4*)&As[c][ty*8];
            float4 a1 = *(const float4*)&As[c][ty*8+4];
            ulonglong2 b01 = *(const ulonglong2*)&Bs[c][tx*8];
            ulonglong2 b23 = *(const ulonglong2*)&Bs[c][tx*8+4];
            unsigned long long bp[4] = {b01.x, b01.y, b23.x, b23.y};
            unsigned long long ap[8];
            ap[0]=dup2(a0.x); ap[1]=dup2(a0.y); ap[2]=dup2(a0.z); ap[3]=dup2(a0.w);
            ap[4]=dup2(a1.x); ap[5]=dup2(a1.y); ap[6]=dup2(a1.z); ap[7]=dup2(a1.w);
            #pragma unroll
            for (int i = 0; i < 8; i++)
                #pragma unroll
                for (int j = 0; j < 4; j++) ffma2(acc2[i][j], ap[i], bp[j]);
        }
        __syncthreads();
    }
    if (!isB) xnA[nr] = (na0 + na1) + (na2 + na3);
    else      xnB[nr] = (na0 + na1) + (na2 + na3);
    __syncthreads();

    float xr[8], xc[8];
    #pragma unroll
    for (int i = 0; i < 8; i++) {
        xr[i] = xnA[ty*8 + i];
        xc[i] = xnB[tx*8 + i];
    }
    #pragma unroll
    for (int i = 0; i < 8; i++) {
        long rbase = ((long)(b*NPT) + row0 + ty*8 + i) * NPT + col0 + tx*8;
        float2 p0 = unpk2(acc2[i][0]);
        float2 p1 = unpk2(acc2[i][1]);
        float2 p2 = unpk2(acc2[i][2]);
        float2 p3 = unpk2(acc2[i][3]);
        uint4 o0, o1;
        o0.x = mapkey(2.f*p0.x - xr[i] - xc[0]);
        o0.y = mapkey(2.f*p0.y - xr[i] - xc[1]);
        o0.z = mapkey(2.f*p1.x - xr[i] - xc[2]);
        o0.w = mapkey(2.f*p1.y - xr[i] - xc[3]);
        o1.x = mapkey(2.f*p2.x - xr[i] - xc[4]);
        o1.y = mapkey(2.f*p2.y - xr[i] - xc[5]);
        o1.z = mapkey(2.f*p3.x - xr[i] - xc[6]);
        o1.w = mapkey(2.f*p3.y - xr[i] - xc[7]);
        *(uint4*)&neg[rbase]     = o0;
        *(uint4*)&neg[rbase + 4] = o1;
    }
}

// ------------------------------------------------------------------ top-20: warp per row, REDUX argmax + per-lane top-4 cache
__global__ __launch_bounds__(256) void topk_kernel(const unsigned* __restrict__ neg, int* __restrict__ idxout) {
    int warp = threadIdx.x >> 5, lane = threadIdx.x & 31;
    long row = (long)blockIdx.x * 8 + warp;
    const unsigned* rp = neg + row * NPT;

    unsigned ck0=0,ck1=0,ck2=0,ck3=0;
    unsigned ci0=0,ci1=0,ci2=0,ci3=0;
    #pragma unroll
    for (int g = 0; g < 8; g++) {
        uint4 kv = *(const uint4*)&rp[g*128 + lane*4];
        unsigned kk[4] = {kv.x, kv.y, kv.z, kv.w};
        #pragma unroll
        for (int q = 0; q < 4; q++) {
            unsigned k = kk[q];
            unsigned gi = (unsigned)(g*128 + lane*4 + q);
            if (k > ck3) {
                if (k > ck0)      { ck3=ck2;ci3=ci2; ck2=ck1;ci2=ci1; ck1=ck0;ci1=ci0; ck0=k;ci0=gi; }
                else if (k > ck1) { ck3=ck2;ci3=ci2; ck2=ck1;ci2=ci1; ck1=k;ci1=gi; }
                else if (k > ck2) { ck3=ck2;ci3=ci2; ck2=k;ci2=gi; }
                else              { ck3=k;ci3=gi; }
            }
        }
    }
    unsigned removed = 0u;   // bit j = 4*g + q
    int navail = 4;
    for (int sel = 0; sel < KNN; sel++) {
        unsigned maxk = __reduce_max_sync(0xffffffffu, ck0);
        unsigned cand = (ck0 == maxk) ? ci0 : 0xffffffffu;
        unsigned widx = __reduce_min_sync(0xffffffffu, cand);
        if (lane == 0) idxout[row*KNN + sel] = (int)widx;
        if (ck0 == maxk && ci0 == widx) {
            int jw = (int)(((widx >> 7) << 2) | (widx & 3u));
            removed |= 1u << jw;
            ck0=ck1;ci0=ci1; ck1=ck2;ci1=ci2; ck2=ck3;ci2=ci3; ck3=0;ci3=0;
            if (--navail == 0) {
                ck0=ck1=ck2=ck3=0; ci0=ci1=ci2=ci3=0;
                for (int g = 0; g < 8; g++) {
                    uint4 kv = *(const uint4*)&rp[g*128 + lane*4];
                    unsigned kk[4] = {kv.x, kv.y, kv.z, kv.w};
                    #pragma unroll
                    for (int q = 0; q < 4; q++) {
                        if ((removed >> (4*g + q)) & 1u) continue;
                        unsigned k = kk[q];
                        unsigned gi = (unsigned)(g*128 + lane*4 + q);
                        if (k > ck3) {
                            if (k > ck0)      { ck3=ck2;ci3=ci2; ck2=ck1;ci2=ci1; ck1=ck0;ci1=ci0; ck0=k;ci0=gi; }
                            else if (k > ck1) { ck3=ck2;ci3=ci2; ck2=ck1;ci2=ci1; ck1=k;ci1=gi; }
                            else if (k > ck2) { ck3=ck2;ci3=ci2; ck2=k;ci2=gi; }
                            else              { ck3=k;ci3=gi; }
                        }
                    }
                }
                navail = 4;
            }
        }
    }
}

// ------------------------------------------------------------------ fused gather + edge conv + BN + leaky + max_k  (c-paired FFMA2)
template <int CIN, int CROW, int COUT, int P, int THREADS, int NPH>
__global__ __launch_bounds__(THREADS, 1)
void conv_kernel(const float* __restrict__ X, const int* __restrict__ idx,
                 const float* __restrict__ w_a, const float* __restrict__ w_b,
                 const float* __restrict__ gam_a, const float* __restrict__ gam_b,
                 const float* __restrict__ bet_a, const float* __restrict__ bet_b,
                 float* __restrict__ out) {
    constexpr int TPP = THREADS / P;
    static_assert(TPP == COUT / 2, "CPT must be 2");
    constexpr int CPH = CROW / NPH;
    constexpr int WST = CROW + 2;
    constexpr int CP  = CPH + 4;
    extern __shared__ float sm[];
    float* w1T = sm;
    float* wdT = w1T + COUT * WST;
    float* nb  = wdT + COUT * WST;
    int* sidx  = (int*)(nb + P * 21 * CP);

    int t = threadIdx.x;
    int b  = blockIdx.x / (NPT / P);
    int n0 = (blockIdx.x % (NPT / P)) * P;
    const float* w   = (b < NB) ? w_a : w_b;
    const float* gam = (b < NB) ? gam_a : gam_b;
    const float* bet = (b < NB) ? bet_a : bet_b;

    for (int i = t; i < COUT * CROW; i += THREADS) {
        int o = i / CROW, c = i % CROW;
        float w1 = (c < CIN) ? w[o * (2*CIN) + c] : 0.f;
        float w2 = (c < CIN) ? w[o * (2*CIN) + CIN + c] : 0.f;
        w1T[o * WST + c] = w1;
        wdT[o * WST + c] = w2 - w1;
    }
    for (int i = t; i < P * KNN; i += THREADS)
        sidx[i] = idx[((long)(b*NPT) + n0) * KNN + i];
    __syncthreads();

    int p  = t / TPP;
    int o0 = t % TPP;
    int o1 = o0 + COUT / 2;
    unsigned long long s0[KNN], s1[KNN];
    unsigned long long u0 = 0ull, u1 = 0ull;
    #pragma unroll
    for (int k = 0; k < KNN; k++) { s0[k] = 0ull; s1[k] = 0ull; }

    const float* nbp = nb + p * 21 * CP;
    constexpr int V4 = CPH / 4;
    for (int ph = 0; ph < NPH; ph++) {
        if (ph > 0) __syncthreads();
        for (int i = t; i < P * 21 * V4; i += THREADS) {
            int c4 = i % V4;
            int vec = i / V4;
            int pp = vec / 21, k = vec % 21;
            int m = (k < KNN) ? sidx[pp*KNN + k] : (n0 + pp);
            float4 v = *(const float4*)&X[((long)(b*NPT) + m) * CROW + ph*CPH + 4*c4];
            *(float4*)&nb[(pp*21 + k) * CP + 4*c4] = v;
        }
        __syncthreads();

        #pragma unroll 1
        for (int c2 = 0; c2 < CPH/2; c2++) {
            int cl = 2 * c2;
            int cg = ph * CPH + cl;
            unsigned long long w1p0 = *(const unsigned long long*)&w1T[o0 * WST + cg];
            unsigned long long w1p1 = *(const unsigned long long*)&w1T[o1 * WST + cg];
            unsigned long long wdp0 = *(const unsigned long long*)&wdT[o0 * WST + cg];
            unsigned long long wdp1 = *(const unsigned long long*)&wdT[o1 * WST + cg];
            unsigned long long ctr = *(const unsigned long long*)&nbp[20 * CP + cl];
            ffma2(u0, wdp0, ctr);
            ffma2(u1, wdp1, ctr);
            #pragma unroll
            for (int k = 0; k < KNN; k++) {
                unsigned long long nbk = *(const unsigned long long*)&nbp[k * CP + cl];
                ffma2(s0[k], w1p0, nbk);
                ffma2(s1[k], w1p1, nbk);
            }
        }
    }

    float inv = rsqrtf(1.0f + 1e-5f);
    int n = n0 + p;
    float* op = &out[((long)(b*NPT) + n) * COUT];
    {
        float2 h = unpk2(s0[0]);
        float v0 = h.x + h.y;
        float mx = v0, mn = v0;
        #pragma unroll
        for (int k = 1; k < KNN; k++) {
            float2 hk = unpk2(s0[k]);
            float vk = hk.x + hk.y;
            mx = fmaxf(mx, vk); mn = fminf(mn, vk);
        }
        float2 up = unpk2(u0);
        float uu = up.x + up.y;
        float g = gam[o0], bt = bet[o0];
        float aa = g * inv;
        float base = ((aa >= 0.f) ? mx : mn) + uu;
        float v = aa * base + bt;
        op[o0] = v >= 0.f ? v : 0.2f * v;
    }
    {
        float2 h = unpk2(s1[0]);
        float v0 = h.x + h.y;
        float mx = v0, mn = v0;
        #pragma unroll
        for (int k = 1; k < KNN; k++) {
            float2 hk = unpk2(s1[k]);
            float vk = hk.x + hk.y;
            mx = fmaxf(mx, vk); mn = fminf(mn, vk);
        }
        float2 up = unpk2(u1);
        float uu = up.x + up.y;
        float g = gam[o1], bt = bet[o1];
        float aa = g * inv;
        float base = ((aa >= 0.f) ? mx : mn) + uu;
        float v = aa * base + bt;
        op[o1] = v >= 0.f ? v : 0.2f * v;
    }
}

// ------------------------------------------------------------------ ew conv on concat(H3,S3) -> emb (packed FMA, 8 points in flight)
__global__ __launch_bounds__(256)
void emb_kernel(const float* __restrict__ H3, const float* __restrict__ S3,
                const float* __restrict__ ew, const float* __restrict__ eg,
                const float* __restrict__ eb, float* __restrict__ emb) {
    extern __shared__ float sm[];
    float* wts  = sm;                 // [256][128]
    float* rows = wts + 256 * 128;    // [8][256]
    int t = threadIdx.x;
    for (int i = t; i < 256 * 128; i += 256) {
        int c = i / 128, o = i % 128;
        wts[c * 128 + o] = ew[o * 256 + c];
    }
    const int NITER = 16;
    int base = blockIdx.x * (8 * NITER);
    int pl = t >> 5;                  // 0..7
    int o4 = (t & 31) * 4;
    float inv = rsqrtf(1.0f + 1e-5f);
    for (int it = 0; it < NITER; it++) {
        __syncthreads();
        int p0 = base + it * 8;
        for (int i = t; i < 8 * 256; i += 256) {
            int pp = i / 256, c = i % 256;
            long pt = p0 + pp;
            rows[pp * 256 + c] = (c < 128) ? H3[pt * 128 + c] : S3[pt * 128 + c - 128];
        }
        __syncthreads();
        unsigned long long acc2[2] = {0ull, 0ull};
        for (int c = 0; c < 256; c++) {
            ulonglong2 wp = *(const ulonglong2*)&wts[c * 128 + o4];
            unsigned long long xd = dup2(rows[pl * 256 + c]);
            ffma2(acc2[0], wp.x, xd);
            ffma2(acc2[1], wp.y, xd);
        }
        float2 axy = unpk2(acc2[0]);
        float2 azw = unpk2(acc2[1]);
        float4 gmv = *(const float4*)&eg[o4];
        float4 btv = *(const float4*)&eb[o4];
        float4 r;
        { float v = gmv.x*inv*axy.x + btv.x; r.x = v>=0.f?v:0.2f*v; }
        { float v = gmv.y*inv*axy.y + btv.y; r.y = v>=0.f?v:0.2f*v; }
        { float v = gmv.z*inv*azw.x + btv.z; r.z = v>=0.f?v:0.2f*v; }
        { float v = gmv.w*inv*azw.y + btv.w; r.w = v>=0.f?v:0.2f*v; }
        long pt = p0 + pl;
        *(float4*)&emb[pt * 128 + o4] = r;
    }
}

// ------------------------------------------------------------------ attention pieces
__global__ void gcfused_kernel(const float* __restrict__ emb, const float* __restrict__ att_w,
                               float* __restrict__ gc) {
    __shared__ float part[8][128];
    __shared__ float es[128];
    int b = blockIdx.x, t = threadIdx.x;      // 1024 threads
    int seg = t >> 7, f = t & 127;
    const float* p = emb + ((long)(b*NPT) + seg*128) * 128 + f;
    float a = 0.f;
    #pragma unroll 4
    for (int n = 0; n < 128; n++) a += p[n * 128];
    part[seg][f] = a;
    __syncthreads();
    if (t < 128) {
        float s = 0.f;
        #pragma unroll
        for (int s8 = 0; s8 < 8; s8++) s += part[s8][t];
        es[t] = s;
    }
    __syncthreads();
    if (t < 128) {
        float gv = 0.f;
        for (int f2 = 0; f2 < 128; f2++) gv += es[f2] * att_w[f2 * 128 + t];
        gc[b * 128 + t] = tanhf(gv * (1.0f / NPT));
    }
}

__global__ void sc_kernel(const float* __restrict__ emb, const float* __restrict__ gc,
                          float* __restrict__ att) {
    int warp = threadIdx.x >> 5, lane = threadIdx.x & 31;
    int pid = blockIdx.x * 4 + warp;
    int b = pid >> 10;
    float a = 0.f;
    #pragma unroll
    for (int j = 0; j < 4; j++) {
        int f = lane + 32 * j;
        a += emb[(long)pid * 128 + f] * gc[b * 128 + f];
    }
    #pragma unroll
    for (int off = 16; off; off >>= 1) a += __shfl_down_sync(0xffffffffu, a, off);
    if (lane == 0) att[pid] = 1.0f / (1.0f + expf(-a));
}

__global__ void pool_part(const float* __restrict__ emb, const float* __restrict__ att,
                          float* __restrict__ part) {
    int b = blockIdx.x, seg = blockIdx.y, f = threadIdx.x;
    const float* p = emb + ((long)(b*NPT) + seg*128) * 128 + f;
    const float* aw = att + b*NPT + seg*128;
    float a = 0.f;
    #pragma unroll 4
    for (int n = 0; n < 128; n++) a += p[n * 128] * aw[n];
    part[(b*8 + seg) * 128 + f] = a;
}

__global__ void pool_fin(const float* __restrict__ part, float* __restrict__ e) {
    int b = blockIdx.x, t = threadIdx.x;
    float a = 0.f;
    #pragma unroll
    for (int s = 0; s < 8; s++) a += part[(b*8 + s) * 128 + t];
    e[b * 128 + t] = a;
}

// ------------------------------------------------------------------ final scoring
__global__ void final_kernel(const float* __restrict__ e, const float* __restrict__ tn_w,
                             const float* __restrict__ tn_wb, const float* __restrict__ tn_bias,
                             const float* __restrict__ fc1_w, const float* __restrict__ fc1_b,
                             const float* __restrict__ sc_w, const float* __restrict__ sc_b,
                             float* __restrict__ out) {
    __shared__ float e1s[128], e2s[128], red[128], ts[16], hs[16];
    int b = blockIdx.x, tid = threadIdx.x;
    e1s[tid] = e[b * 128 + tid];
    e2s[tid] = e[(b + 8) * 128 + tid];
    __syncthreads();
    for (int tt = 0; tt < 16; tt++) {
        float inner = 0.f;
        const float* wrow = tn_w + (long)tid * 128 * 16 + tt;
        for (int gI = 0; gI < 128; gI++) inner += wrow[gI * 16] * e2s[gI];
        red[tid] = e1s[tid] * inner;
        __syncthreads();
        for (int s2 = 64; s2; s2 >>= 1) {
            if (tid < s2) red[tid] += red[tid + s2];
            __syncthreads();
        }
        if (tid == 0) ts[tt] = red[0];
        __syncthreads();
    }
    if (tid < 16) {
        float blk = 0.f;
        for (int c = 0; c < 128; c++) blk += tn_wb[tid * 256 + c] * e1s[c];
        for (int c = 0; c < 128; c++) blk += tn_wb[tid * 256 + 128 + c] * e2s[c];
        float v = ts[tid] + blk + tn_bias[tid];
        ts[tid] = v > 0.f ? v : 0.f;
    }
    __syncthreads();
    if (tid < 16) {
        float h = fc1_b[tid];
        for (int u2 = 0; u2 < 16; u2++) h += fc1_w[tid * 16 + u2] * ts[u2];
        hs[tid] = h > 0.f ? h : 0.f;
    }
    __syncthreads();
    if (tid == 0) {
        float z = sc_b[0];
        for (int u2 = 0; u2 < 16; u2++) z += sc_w[u2] * hs[u2];
        out[b] = 1.0f / (1.0f + expf(-z));
    }
}

// ------------------------------------------------------------------ host
template <typename T>
static float* symaddr(T& sym_) {
    void* p = nullptr;
    cudaGetSymbolAddress(&p, sym_);
    return (float*)p;
}

extern "C" void kernel_launch(void* const* d_in, const int* in_sizes, int n_in,
                              void* d_out, int out_size) {
    (void)in_sizes; (void)n_in; (void)out_size;
    const float* f1    = (const float*)d_in[0];
    const float* f2    = (const float*)d_in[1];
    const float* sw1   = (const float*)d_in[2];
    const float* sg1   = (const float*)d_in[3];
    const float* sb1   = (const float*)d_in[4];
    const float* fw1   = (const float*)d_in[5];
    const float* fg1   = (const float*)d_in[6];
    const float* fb1   = (const float*)d_in[7];
    const float* sw2   = (const float*)d_in[8];
    const float* sg2   = (const float*)d_in[9];
    const float* sb2   = (const float*)d_in[10];
    const float* fw2   = (const float*)d_in[11];
    const float* fg2   = (const float*)d_in[12];
    const float* fb2   = (const float*)d_in[13];
    const float* sw3   = (const float*)d_in[14];
    const float* sg3   = (const float*)d_in[15];
    const float* sb3   = (const float*)d_in[16];
    const float* fw3   = (const float*)d_in[17];
    const float* fg3   = (const float*)d_in[18];
    const float* fb3   = (const float*)d_in[19];
    const float* ew    = (const float*)d_in[20];
    const float* eg    = (const float*)d_in[21];
    const float* ebv   = (const float*)d_in[22];
    const float* att_w = (const float*)d_in[23];
    const float* tn_w  = (const float*)d_in[24];
    const float* tn_wb = (const float*)d_in[25];
    const float* tn_b  = (const float*)d_in[26];
    const float* fc1_w = (const float*)d_in[27];
    const float* fc1_b = (const float*)d_in[28];
    const float* sc_w  = (const float*)d_in[29];
    const float* sc_b  = (const float*)d_in[30];
    float* out = (float*)d_out;

    unsigned* negp = (unsigned*)symaddr(g_neg);
    int*   idxp  = (int*)symaddr(g_idx);
    float* x0p   = symaddr(g_x0);
    float* s0p   = symaddr(g_s0);
    float* hAp   = symaddr(g_hA);
    float* hBp   = symaddr(g_hB);
    float* h3p   = symaddr(g_h3);
    float* embp  = symaddr(g_emb);
    float* partp = symaddr(g_part);
    float* gcp   = symaddr(g_gc);
    float* ep    = symaddr(g_e);

    unsigned* negB = negp + (size_t)NROW * NPT;
    int* idxB = idxp + NROW * KNN;
    float* hA_B = hAp + NROW * 64;

    const int SM_C2 = (2*64*66   + 8*21*68) * 4 + 8*KNN*4;    // conv<64,64,64,8,256,1>
    const int SM_C3 = (2*128*66  + 8*21*68) * 4 + 8*KNN*4;    // conv<64,64,128,8,512,1>
    const int SM_C4 = (2*64*130  + 16*21*68) * 4 + 16*KNN*4;  // conv<128,128,64,16,512,2>
    const int SM_EW = (256*128 + 8*256) * 4;

    cudaFuncSetAttribute(conv_kernel<64,64,64,8,256,1>,    cudaFuncAttributeMaxDynamicSharedMemorySize, SM_C2);
    cudaFuncSetAttribute(conv_kernel<64,64,128,8,512,1>,   cudaFuncAttributeMaxDynamicSharedMemorySize, SM_C3);
    cudaFuncSetAttribute(conv_kernel<128,128,64,16,512,2>, cudaFuncAttributeMaxDynamicSharedMemorySize, SM_C4);
    cudaFuncSetAttribute(emb_kernel,                       cudaFuncAttributeMaxDynamicSharedMemorySize, SM_EW);

    static cudaStream_t sB = 0;
    static cudaEvent_t evFork = 0, evJoin = 0;
    if (!sB) {
        cudaStreamCreateWithFlags(&sB, cudaStreamNonBlocking);
        cudaEventCreateWithFlags(&evFork, cudaEventDisableTiming);
        cudaEventCreateWithFlags(&evJoin, cudaEventDisableTiming);
    }

    transposeX_kernel<<<(NB*3*NPT + 255) / 256, 256>>>(f1, f2, x0p);
    transposeS_kernel<<<dim3(NPT/32, 4, NB), dim3(32, 8)>>>(f1, f2, s0p);
    cudaEventRecord(evFork, 0);
    cudaStreamWaitEvent(sB, evFork, 0);

    // ---- layer 1: stream 0 = fused xyz knn+conv, then sem batches [0,SPL);
    //               stream sB = sem batches [SPL,NB) ----
    knnconv1_kernel<<<NROW/16, 512>>>(x0p, sw1, sg1, sb1, hAp);

    dist_kernel<128><<<dim3(8,8,SPL), 256>>>(s0p, negB);
    topk_kernel<<<SPL*NPT/8, 256>>>(negB, idxB);
    conv_kernel<128,128,64,16,512,2><<<SPL*NPT/16, 512, SM_C4>>>(s0p, idxB, fw1, fw1, fg1, fg1, fb1, fb1, hA_B);

    {
        const int RB = NB - SPL;   // 9 batches on sB
        const float* s0q = s0p + (size_t)SPL * NPT * 128;
        unsigned* negq = negB + (size_t)SPL * NPT * NPT;
        int* idxq = idxB + SPL * NPT * KNN;
        float* hAq = hA_B + SPL * NPT * 64;
        dist_kernel<128><<<dim3(8,8,RB), 256, 0, sB>>>(s0q, negq);
        topk_kernel<<<RB*NPT/8, 256, 0, sB>>>(negq, idxq);
        conv_kernel<128,128,64,16,512,2><<<RB*NPT/16, 512, SM_C4, sB>>>(s0q, idxq, fw1, fw1, fg1, fg1, fb1, fb1, hAq);
    }

    cudaEventRecord(evJoin, sB);
    cudaStreamWaitEvent(0, evJoin, 0);

    // ---- layer 2 (merged NB2, 64 -> 64) ----
    dist_kernel<64><<<dim3(8,8,NB2), 256>>>(hAp, negp);
    topk_kernel<<<NROW2/8, 256>>>(negp, idxp);
    conv_kernel<64,64,64,8,256,1><<<NB2*NPT/8, 256, SM_C2>>>(hAp, idxp, sw2, fw2, sg2, fg2, sb2, fb2, hBp);

    // ---- layer 3 (merged NB2, 64 -> 128) ----
    dist_kernel<64><<<dim3(8,8,NB2), 256>>>(hBp, negp);
    topk_kernel<<<NROW2/8, 256>>>(negp, idxp);
    conv_kernel<64,64,128,8,512,1><<<NB2*NPT/8, 512, SM_C3>>>(hBp, idxp, sw3, fw3, sg3, fg3, sb3, fb3, h3p);

    // ---- fuse + attention (all 16 batches) ----
    emb_kernel<<<NROW/128, 256, SM_EW>>>(h3p, h3p + NROW*128, ew, eg, ebv, embp);

    float* att_out = out + 8;                       // att1 (b 0..7) then att2 (b 8..15), contiguous
    gcfused_kernel<<<NB, 1024>>>(embp, att_w, gcp);
    sc_kernel<<<NROW/4, 128>>>(embp, gcp, att_out);
    pool_part<<<dim3(NB, 8), 128>>>(embp, att_out, partp);
    pool_fin<<<NB, 128>>>(partp, ep);

    final_kernel<<<BB, 128>>>(ep, tn_w, tn_wb, tn_b, fc1_w, fc1_b, sc_w, sc_b, out);
}

// round 17
// speedup vs baseline: 1.1140x; 1.0243x over previous
#include <cuda_runtime.h>
#include <math.h>
#include <stdint.h>

#define BB   8
#define NB   16          // batches per graph-pair set
#define NB2  32          // both chains merged (xyz batches 0-15, sem 16-31)
#define NPT  1024
#define KNN  20
#define NROW (NB*NPT)    // 16384
#define NROW2 (NB2*NPT)  // 32768
#define SPL  7           // sem layer-1 batches assigned to stream 0

// ------------------------------------------------------------------ packed fp32x2 helpers
__device__ __forceinline__ void ffma2(unsigned long long& d, unsigned long long a, unsigned long long b) {
    asm("fma.rn.f32x2 %0, %1, %2, %0;" : "+l"(d) : "l"(a), "l"(b));
}
__device__ __forceinline__ unsigned long long dup2(float x) {
    unsigned long long r;
    asm("mov.b64 %0, {%1, %1};" : "=l"(r) : "f"(x));
    return r;
}
__device__ __forceinline__ float2 unpk2(unsigned long long v) {
    float2 r;
    asm("mov.b64 {%0, %1}, %2;" : "=f"(r.x), "=f"(r.y) : "l"(v));
    return r;
}
__device__ __forceinline__ unsigned mapkey(float v) {
    unsigned u = __float_as_uint(v);
    return (u & 0x80000000u) ? ~u : (u | 0x80000000u);   // order-preserving; real keys > 0
}

// ------------------------------------------------------------------ scratch
__device__ unsigned g_neg[(size_t)NROW2*NPT];   // mapped-key distance matrix
__device__ int   g_idx[NROW2*KNN];
__device__ float g_x0 [NROW*4];
__device__ float g_s0 [NROW*128];
__device__ float g_hA [NROW2*64];
__device__ float g_hB [NROW2*64];
__device__ float g_h3 [NROW2*128];     // layer-3 out: xyz half then sem half
__device__ float g_emb[NROW*128];
__device__ float g_part[NB*8*128];
__device__ float g_gc  [NB*128];
__device__ float g_e   [NB*128];

// ------------------------------------------------------------------ transposes
__global__ void transposeX_kernel(const float* __restrict__ f1, const float* __restrict__ f2,
                                  float* __restrict__ x0) {
    int j = blockIdx.x * blockDim.x + threadIdx.x;     // over NB*3*NPT
    if (j >= NB * 3 * NPT) return;
    int n = j % NPT;
    int c = (j / NPT) % 3;
    int b = j / (3 * NPT);
    const float* in = (b < BB) ? f1 : f2;
    float v = in[((long)(b & 7) * 131 + c) * NPT + n];
    x0[(b*NPT + n)*4 + c] = v;
    if (c == 0) x0[(b*NPT + n)*4 + 3] = 0.0f;
}
__global__ void transposeS_kernel(const float* __restrict__ f1, const float* __restrict__ f2,
                                  float* __restrict__ s0) {
    __shared__ float tile[32][33];
    int b  = blockIdx.z;
    int c0 = blockIdx.y * 32;
    int n0 = blockIdx.x * 32;
    const float* in = (b < BB) ? f1 : f2;
    int tx = threadIdx.x, ty = threadIdx.y;   // 32 x 8
    #pragma unroll
    for (int i = 0; i < 32; i += 8)
        tile[ty + i][tx] = in[((long)(b & 7) * 131 + 3 + c0 + ty + i) * NPT + n0 + tx];
    __syncthreads();
    #pragma unroll
    for (int i = 0; i < 32; i += 8)
        s0[((long)(b*NPT) + n0 + ty + i) * 128 + c0 + tx] = tile[tx][ty + i];
}

// ------------------------------------------------------------------ fused KNN + edge conv for xyz layer 1 (C=4)
__global__ __launch_bounds__(512) void knnconv1_kernel(const float* __restrict__ X,
                                                       const float* __restrict__ w,
                                                       const float* __restrict__ gam,
                                                       const float* __restrict__ bet,
                                                       float* __restrict__ out) {
    __shared__ float4 pts[NPT];
    __shared__ float xxc[NPT];
    __shared__ float w1s[64*4], wds[64*4];
    int t = threadIdx.x;
    int warp = t >> 5, lane = t & 31;
    int b  = blockIdx.x / (NPT / 16);
    int r0 = (blockIdx.x % (NPT / 16)) * 16;
    const float4* Xb = (const float4*)(X + (long)b * NPT * 4);
    for (int i = t; i < NPT; i += 512) {
        float4 p = pts[i] = Xb[i];
        float a = 0.f;
        a = fmaf(p.x, p.x, a); a = fmaf(p.y, p.y, a);
        a = fmaf(p.z, p.z, a); a = fmaf(p.w, p.w, a);
        xxc[i] = a;
    }
    for (int i = t; i < 64*3; i += 512) {
        int o = i / 3, c = i % 3;
        float w1 = w[o*6 + c];
        w1s[o*4 + c] = w1;
        wds[o*4 + c] = w[o*6 + 3 + c] - w1;
    }
    __syncthreads();
    long rowg = (long)(b * NPT) + r0 + warp;
    float4 rv = pts[r0 + warp];
    float xxr = xxc[r0 + warp];

    unsigned key[32];
    #pragma unroll
    for (int j = 0; j < 32; j++) {
        int col = lane + 32 * j;
        float4 pv = pts[col];
        float acc = 0.f;
        acc = fmaf(rv.x, pv.x, acc); acc = fmaf(rv.y, pv.y, acc);
        acc = fmaf(rv.z, pv.z, acc); acc = fmaf(rv.w, pv.w, acc);
        key[j] = mapkey(2.f * acc - xxr - xxc[col]);
    }

    int o0 = lane, o1 = lane + 32;
    float w10x = w1s[o0*4], w10y = w1s[o0*4+1], w10z = w1s[o0*4+2];
    float w11x = w1s[o1*4], w11y = w1s[o1*4+1], w11z = w1s[o1*4+2];
    float u0 = 0.f, u1 = 0.f;
    u0 = fmaf(wds[o0*4], rv.x, u0); u0 = fmaf(wds[o0*4+1], rv.y, u0); u0 = fmaf(wds[o0*4+2], rv.z, u0);
    u1 = fmaf(wds[o1*4], rv.x, u1); u1 = fmaf(wds[o1*4+1], rv.y, u1); u1 = fmaf(wds[o1*4+2], rv.z, u1);
    float mx0 = 0.f, mn0 = 0.f, mx1 = 0.f, mn1 = 0.f;

    unsigned ck0=0,ck1=0,ck2=0,ck3=0;
    unsigned ci0=0,ci1=0,ci2=0,ci3=0;
    #pragma unroll
    for (int j = 0; j < 32; j++) {
        unsigned k = key[j];
        unsigned gi = (unsigned)(lane + 32*j);
        if (k > ck3) {
            if (k > ck0)      { ck3=ck2;ci3=ci2; ck2=ck1;ci2=ci1; ck1=ck0;ci1=ci0; ck0=k;ci0=gi; }
            else if (k > ck1) { ck3=ck2;ci3=ci2; ck2=ck1;ci2=ci1; ck1=k;ci1=gi; }
            else if (k > ck2) { ck3=ck2;ci3=ci2; ck2=k;ci2=gi; }
            else              { ck3=k;ci3=gi; }
        }
    }
    unsigned removed = 0u;
    int navail = 4;
    for (int sel = 0; sel < KNN; sel++) {
        unsigned maxk = __reduce_max_sync(0xffffffffu, ck0);
        unsigned cand = (ck0 == maxk) ? ci0 : 0xffffffffu;
        unsigned widx = __reduce_min_sync(0xffffffffu, cand);
        {
            float4 pv = pts[widx];
            float sk0 = 0.f, sk1 = 0.f;
            sk0 = fmaf(w10x, pv.x, sk0); sk0 = fmaf(w10y, pv.y, sk0); sk0 = fmaf(w10z, pv.z, sk0);
            sk1 = fmaf(w11x, pv.x, sk1); sk1 = fmaf(w11y, pv.y, sk1); sk1 = fmaf(w11z, pv.z, sk1);
            if (sel == 0) { mx0 = mn0 = sk0; mx1 = mn1 = sk1; }
            else {
                mx0 = fmaxf(mx0, sk0); mn0 = fminf(mn0, sk0);
                mx1 = fmaxf(mx1, sk1); mn1 = fminf(mn1, sk1);
            }
        }
        if (ck0 == maxk && ci0 == widx) {
            removed |= 1u << (widx >> 5);
            ck0=ck1;ci0=ci1; ck1=ck2;ci1=ci2; ck2=ck3;ci2=ci3; ck3=0;ci3=0;
            if (--navail == 0) {
                ck0=ck1=ck2=ck3=0; ci0=ci1=ci2=ci3=0;
                #pragma unroll
                for (int j = 0; j < 32; j++) {
                    if ((removed >> j) & 1u) continue;
                    unsigned k = key[j];
                    unsigned gi = (unsigned)(lane + 32*j);
                    if (k > ck3) {
                        if (k > ck0)      { ck3=ck2;ci3=ci2; ck2=ck1;ci2=ci1; ck1=ck0;ci1=ci0; ck0=k;ci0=gi; }
                        else if (k > ck1) { ck3=ck2;ci3=ci2; ck2=ck1;ci2=ci1; ck1=k;ci1=gi; }
                        else if (k > ck2) { ck3=ck2;ci3=ci2; ck2=k;ci2=gi; }
                        else              { ck3=k;ci3=gi; }
                    }
                }
                navail = 4;
            }
        }
    }
    float inv = rsqrtf(1.0f + 1e-5f);
    {
        float g = gam[o0], bt = bet[o0];
        float aa = g * inv;
        float base = ((aa >= 0.f) ? mx0 : mn0) + u0;
        float v = aa * base + bt;
        out[rowg * 64 + o0] = v >= 0.f ? v : 0.2f * v;
    }
    {
        float g = gam[o1], bt = bet[o1];
        float aa = g * inv;
        float base = ((aa >= 0.f) ? mx1 : mn1) + u1;
        float v = aa * base + bt;
        out[rowg * 64 + o1] = v >= 0.f ? v : 0.2f * v;
    }
}

// ------------------------------------------------------------------ neg distance -> mapped u32 keys, fused norms
// __launch_bounds__(256,2): cap regs at 128 -> 2 CTAs/SM (was 170 regs, 1 CTA/SM, issue 33%).
// dup2 broadcasts computed just-in-time per row to shrink the live set (same instr count).
template <int CROW>
__global__ __launch_bounds__(256, 2) void dist_kernel(const float* __restrict__ X,
                                                      unsigned* __restrict__ neg) {
    constexpr int TC = 16;
    constexpr int LDW = 132;
    __shared__ float As[TC][LDW];
    __shared__ float Bs[TC][LDW];
    __shared__ float xnA[128], xnB[128];
    int b = blockIdx.z;
    int row0 = blockIdx.y * 128;
    int col0 = blockIdx.x * 128;
    int t = threadIdx.x;
    int tx = t & 15, ty = t >> 4;
    int nr = t & 127;
    bool isB = t >= 128;
    float na0 = 0.f, na1 = 0.f, na2 = 0.f, na3 = 0.f;
    unsigned long long acc2[8][4];
    #pragma unroll
    for (int i = 0; i < 8; i++)
        #pragma unroll
        for (int j = 0; j < 4; j++) acc2[i][j] = 0ull;

    for (int c0 = 0; c0 < CROW; c0 += TC) {
        constexpr int NLD = (128 * TC) / 256;
        #pragma unroll
        for (int l = 0; l < NLD; l++) {
            int i = t + l * 256;
            int r = i / TC, c = i % TC;
            As[c][r] = X[((long)(b*NPT) + row0 + r) * CROW + c0 + c];
            Bs[c][r] = X[((long)(b*NPT) + col0 + r) * CROW + c0 + c];
        }
        __syncthreads();
        {
            const float (*T)[LDW] = isB ? Bs : As;
            #pragma unroll
            for (int cl = 0; cl < TC; cl += 4) {
                float v0 = T[cl+0][nr], v1 = T[cl+1][nr];
                float v2 = T[cl+2][nr], v3 = T[cl+3][nr];
                na0 = fmaf(v0, v0, na0); na1 = fmaf(v1, v1, na1);
                na2 = fmaf(v2, v2, na2); na3 = fmaf(v3, v3, na3);
            }
        }
        #pragma unroll
        for (int c = 0; c < TC; c++) {
            float4 a0 = *(const float4*)&As[c][ty*8];
            float4 a1 = *(const float4*)&As[c][ty*8+4];
            ulonglong2 b01 = *(const ulonglong2*)&Bs[c][tx*8];
            ulonglong2 b23 = *(const ulonglong2*)&Bs[c][tx*8+4];
            unsigned long long bp0 = b01.x, bp1 = b01.y, bp2 = b23.x, bp3 = b23.y;
            float aa[8] = {a0.x, a0.y, a0.z, a0.w, a1.x, a1.y, a1.z, a1.w};
            #pragma unroll
            for (int i = 0; i < 8; i++) {
                unsigned long long ai = dup2(aa[i]);
                ffma2(acc2[i][0], ai, bp0);
                ffma2(acc2[i][1], ai, bp1);
                ffma2(acc2[i][2], ai, bp2);
                ffma2(acc2[i][3], ai, bp3);
            }
        }
        __syncthreads();
    }
    if (!isB) xnA[nr] = (na0 + na1) + (na2 + na3);
    else      xnB[nr] = (na0 + na1) + (na2 + na3);
    __syncthreads();

    float xr[8], xc[8];
    #pragma unroll
    for (int i = 0; i < 8; i++) {
        xr[i] = xnA[ty*8 + i];
        xc[i] = xnB[tx*8 + i];
    }
    #pragma unroll
    for (int i = 0; i < 8; i++) {
        long rbase = ((long)(b*NPT) + row0 + ty*8 + i) * NPT + col0 + tx*8;
        float2 p0 = unpk2(acc2[i][0]);
        float2 p1 = unpk2(acc2[i][1]);
        float2 p2 = unpk2(acc2[i][2]);
        float2 p3 = unpk2(acc2[i][3]);
        uint4 o0, o1;
        o0.x = mapkey(2.f*p0.x - xr[i] - xc[0]);
        o0.y = mapkey(2.f*p0.y - xr[i] - xc[1]);
        o0.z = mapkey(2.f*p1.x - xr[i] - xc[2]);
        o0.w = mapkey(2.f*p1.y - xr[i] - xc[3]);
        o1.x = mapkey(2.f*p2.x - xr[i] - xc[4]);
        o1.y = mapkey(2.f*p2.y - xr[i] - xc[5]);
        o1.z = mapkey(2.f*p3.x - xr[i] - xc[6]);
        o1.w = mapkey(2.f*p3.y - xr[i] - xc[7]);
        *(uint4*)&neg[rbase]     = o0;
        *(uint4*)&neg[rbase + 4] = o1;
    }
}

// ------------------------------------------------------------------ top-20: warp per row, REDUX argmax + per-lane top-4 cache
__global__ __launch_bounds__(256) void topk_kernel(const unsigned* __restrict__ neg, int* __restrict__ idxout) {
    int warp = threadIdx.x >> 5, lane = threadIdx.x & 31;
    long row = (long)blockIdx.x * 8 + warp;
    const unsigned* rp = neg + row * NPT;

    unsigned ck0=0,ck1=0,ck2=0,ck3=0;
    unsigned ci0=0,ci1=0,ci2=0,ci3=0;
    #pragma unroll
    for (int g = 0; g < 8; g++) {
        uint4 kv = *(const uint4*)&rp[g*128 + lane*4];
        unsigned kk[4] = {kv.x, kv.y, kv.z, kv.w};
        #pragma unroll
        for (int q = 0; q < 4; q++) {
            unsigned k = kk[q];
            unsigned gi = (unsigned)(g*128 + lane*4 + q);
            if (k > ck3) {
                if (k > ck0)      { ck3=ck2;ci3=ci2; ck2=ck1;ci2=ci1; ck1=ck0;ci1=ci0; ck0=k;ci0=gi; }
                else if (k > ck1) { ck3=ck2;ci3=ci2; ck2=ck1;ci2=ci1; ck1=k;ci1=gi; }
                else if (k > ck2) { ck3=ck2;ci3=ci2; ck2=k;ci2=gi; }
                else              { ck3=k;ci3=gi; }
            }
        }
    }
    unsigned removed = 0u;   // bit j = 4*g + q
    int navail = 4;
    for (int sel = 0; sel < KNN; sel++) {
        unsigned maxk = __reduce_max_sync(0xffffffffu, ck0);
        unsigned cand = (ck0 == maxk) ? ci0 : 0xffffffffu;
        unsigned widx = __reduce_min_sync(0xffffffffu, cand);
        if (lane == 0) idxout[row*KNN + sel] = (int)widx;
        if (ck0 == maxk && ci0 == widx) {
            int jw = (int)(((widx >> 7) << 2) | (widx & 3u));
            removed |= 1u << jw;
            ck0=ck1;ci0=ci1; ck1=ck2;ci1=ci2; ck2=ck3;ci2=ci3; ck3=0;ci3=0;
            if (--navail == 0) {
                ck0=ck1=ck2=ck3=0; ci0=ci1=ci2=ci3=0;
                for (int g = 0; g < 8; g++) {
                    uint4 kv = *(const uint4*)&rp[g*128 + lane*4];
                    unsigned kk[4] = {kv.x, kv.y, kv.z, kv.w};
                    #pragma unroll
                    for (int q = 0; q < 4; q++) {
                        if ((removed >> (4*g + q)) & 1u) continue;
                        unsigned k = kk[q];
                        unsigned gi = (unsigned)(g*128 + lane*4 + q);
                        if (k > ck3) {
                            if (k > ck0)      { ck3=ck2;ci3=ci2; ck2=ck1;ci2=ci1; ck1=ck0;ci1=ci0; ck0=k;ci0=gi; }
                            else if (k > ck1) { ck3=ck2;ci3=ci2; ck2=ck1;ci2=ci1; ck1=k;ci1=gi; }
                            else if (k > ck2) { ck3=ck2;ci3=ci2; ck2=k;ci2=gi; }
                            else              { ck3=k;ci3=gi; }
                        }
                    }
                }
                navail = 4;
            }
        }
    }
}

// ------------------------------------------------------------------ fused gather + edge conv + BN + leaky + max_k  (c-paired FFMA2)
template <int CIN, int CROW, int COUT, int P, int THREADS, int NPH>
__global__ __launch_bounds__(THREADS, 1)
void conv_kernel(const float* __restrict__ X, const int* __restrict__ idx,
                 const float* __restrict__ w_a, const float* __restrict__ w_b,
                 const float* __restrict__ gam_a, const float* __restrict__ gam_b,
                 const float* __restrict__ bet_a, const float* __restrict__ bet_b,
                 float* __restrict__ out) {
    constexpr int TPP = THREADS / P;
    static_assert(TPP == COUT / 2, "CPT must be 2");
    constexpr int CPH = CROW / NPH;
    constexpr int WST = CROW + 2;
    constexpr int CP  = CPH + 4;
    extern __shared__ float sm[];
    float* w1T = sm;
    float* wdT = w1T + COUT * WST;
    float* nb  = wdT + COUT * WST;
    int* sidx  = (int*)(nb + P * 21 * CP);

    int t = threadIdx.x;
    int b  = blockIdx.x / (NPT / P);
    int n0 = (blockIdx.x % (NPT / P)) * P;
    const float* w   = (b < NB) ? w_a : w_b;
    const float* gam = (b < NB) ? gam_a : gam_b;
    const float* bet = (b < NB) ? bet_a : bet_b;

    for (int i = t; i < COUT * CROW; i += THREADS) {
        int o = i / CROW, c = i % CROW;
        float w1 = (c < CIN) ? w[o * (2*CIN) + c] : 0.f;
        float w2 = (c < CIN) ? w[o * (2*CIN) + CIN + c] : 0.f;
        w1T[o * WST + c] = w1;
        wdT[o * WST + c] = w2 - w1;
    }
    for (int i = t; i < P * KNN; i += THREADS)
        sidx[i] = idx[((long)(b*NPT) + n0) * KNN + i];
    __syncthreads();

    int p  = t / TPP;
    int o0 = t % TPP;
    int o1 = o0 + COUT / 2;
    unsigned long long s0[KNN], s1[KNN];
    unsigned long long u0 = 0ull, u1 = 0ull;
    #pragma unroll
    for (int k = 0; k < KNN; k++) { s0[k] = 0ull; s1[k] = 0ull; }

    const float* nbp = nb + p * 21 * CP;
    constexpr int V4 = CPH / 4;
    for (int ph = 0; ph < NPH; ph++) {
        if (ph > 0) __syncthreads();
        for (int i = t; i < P * 21 * V4; i += THREADS) {
            int c4 = i % V4;
            int vec = i / V4;
            int pp = vec / 21, k = vec % 21;
            int m = (k < KNN) ? sidx[pp*KNN + k] : (n0 + pp);
            float4 v = *(const float4*)&X[((long)(b*NPT) + m) * CROW + ph*CPH + 4*c4];
            *(float4*)&nb[(pp*21 + k) * CP + 4*c4] = v;
        }
        __syncthreads();

        #pragma unroll 1
        for (int c2 = 0; c2 < CPH/2; c2++) {
            int cl = 2 * c2;
            int cg = ph * CPH + cl;
            unsigned long long w1p0 = *(const unsigned long long*)&w1T[o0 * WST + cg];
            unsigned long long w1p1 = *(const unsigned long long*)&w1T[o1 * WST + cg];
            unsigned long long wdp0 = *(const unsigned long long*)&wdT[o0 * WST + cg];
            unsigned long long wdp1 = *(const unsigned long long*)&wdT[o1 * WST + cg];
            unsigned long long ctr = *(const unsigned long long*)&nbp[20 * CP + cl];
            ffma2(u0, wdp0, ctr);
            ffma2(u1, wdp1, ctr);
            #pragma unroll
            for (int k = 0; k < KNN; k++) {
                unsigned long long nbk = *(const unsigned long long*)&nbp[k * CP + cl];
                ffma2(s0[k], w1p0, nbk);
                ffma2(s1[k], w1p1, nbk);
            }
        }
    }

    float inv = rsqrtf(1.0f + 1e-5f);
    int n = n0 + p;
    float* op = &out[((long)(b*NPT) + n) * COUT];
    {
        float2 h = unpk2(s0[0]);
        float v0 = h.x + h.y;
        float mx = v0, mn = v0;
        #pragma unroll
        for (int k = 1; k < KNN; k++) {
            float2 hk = unpk2(s0[k]);
            float vk = hk.x + hk.y;
            mx = fmaxf(mx, vk); mn = fminf(mn, vk);
        }
        float2 up = unpk2(u0);
        float uu = up.x + up.y;
        float g = gam[o0], bt = bet[o0];
        float aa = g * inv;
        float base = ((aa >= 0.f) ? mx : mn) + uu;
        float v = aa * base + bt;
        op[o0] = v >= 0.f ? v : 0.2f * v;
    }
    {
        float2 h = unpk2(s1[0]);
        float v0 = h.x + h.y;
        float mx = v0, mn = v0;
        #pragma unroll
        for (int k = 1; k < KNN; k++) {
            float2 hk = unpk2(s1[k]);
            float vk = hk.x + hk.y;
            mx = fmaxf(mx, vk); mn = fminf(mn, vk);
        }
        float2 up = unpk2(u1);
        float uu = up.x + up.y;
        float g = gam[o1], bt = bet[o1];
        float aa = g * inv;
        float base = ((aa >= 0.f) ? mx : mn) + uu;
        float v = aa * base + bt;
        op[o1] = v >= 0.f ? v : 0.2f * v;
    }
}

// ------------------------------------------------------------------ ew conv on concat(H3,S3) -> emb (packed FMA, 8 points in flight)
__global__ __launch_bounds__(256)
void emb_kernel(const float* __restrict__ H3, const float* __restrict__ S3,
                const float* __restrict__ ew, const float* __restrict__ eg,
                const float* __restrict__ eb, float* __restrict__ emb) {
    extern __shared__ float sm[];
    float* wts  = sm;                 // [256][128]
    float* rows = wts + 256 * 128;    // [8][256]
    int t = threadIdx.x;
    for (int i = t; i < 256 * 128; i += 256) {
        int c = i / 128, o = i % 128;
        wts[c * 128 + o] = ew[o * 256 + c];
    }
    const int NITER = 16;
    int base = blockIdx.x * (8 * NITER);
    int pl = t >> 5;                  // 0..7
    int o4 = (t & 31) * 4;
    float inv = rsqrtf(1.0f + 1e-5f);
    for (int it = 0; it < NITER; it++) {
        __syncthreads();
        int p0 = base + it * 8;
        for (int i = t; i < 8 * 256; i += 256) {
            int pp = i / 256, c = i % 256;
            long pt = p0 + pp;
            rows[pp * 256 + c] = (c < 128) ? H3[pt * 128 + c] : S3[pt * 128 + c - 128];
        }
        __syncthreads();
        unsigned long long acc2[2] = {0ull, 0ull};
        for (int c = 0; c < 256; c++) {
            ulonglong2 wp = *(const ulonglong2*)&wts[c * 128 + o4];
            unsigned long long xd = dup2(rows[pl * 256 + c]);
            ffma2(acc2[0], wp.x, xd);
            ffma2(acc2[1], wp.y, xd);
        }
        float2 axy = unpk2(acc2[0]);
        float2 azw = unpk2(acc2[1]);
        float4 gmv = *(const float4*)&eg[o4];
        float4 btv = *(const float4*)&eb[o4];
        float4 r;
        { float v = gmv.x*inv*axy.x + btv.x; r.x = v>=0.f?v:0.2f*v; }
        { float v = gmv.y*inv*axy.y + btv.y; r.y = v>=0.f?v:0.2f*v; }
        { float v = gmv.z*inv*azw.x + btv.z; r.z = v>=0.f?v:0.2f*v; }
        { float v = gmv.w*inv*azw.y + btv.w; r.w = v>=0.f?v:0.2f*v; }
        long pt = p0 + pl;
        *(float4*)&emb[pt * 128 + o4] = r;
    }
}

// ------------------------------------------------------------------ attention pieces
__global__ void gcfused_kernel(const float* __restrict__ emb, const float* __restrict__ att_w,
                               float* __restrict__ gc) {
    __shared__ float part[8][128];
    __shared__ float es[128];
    int b = blockIdx.x, t = threadIdx.x;      // 1024 threads
    int seg = t >> 7, f = t & 127;
    const float* p = emb + ((long)(b*NPT) + seg*128) * 128 + f;
    float a = 0.f;
    #pragma unroll 4
    for (int n = 0; n < 128; n++) a += p[n * 128];
    part[seg][f] = a;
    __syncthreads();
    if (t < 128) {
        float s = 0.f;
        #pragma unroll
        for (int s8 = 0; s8 < 8; s8++) s += part[s8][t];
        es[t] = s;
    }
    __syncthreads();
    if (t < 128) {
        float gv = 0.f;
        for (int f2 = 0; f2 < 128; f2++) gv += es[f2] * att_w[f2 * 128 + t];
        gc[b * 128 + t] = tanhf(gv * (1.0f / NPT));
    }
}

__global__ void sc_kernel(const float* __restrict__ emb, const float* __restrict__ gc,
                          float* __restrict__ att) {
    int warp = threadIdx.x >> 5, lane = threadIdx.x & 31;
    int pid = blockIdx.x * 4 + warp;
    int b = pid >> 10;
    float a = 0.f;
    #pragma unroll
    for (int j = 0; j < 4; j++) {
        int f = lane + 32 * j;
        a += emb[(long)pid * 128 + f] * gc[b * 128 + f];
    }
    #pragma unroll
    for (int off = 16; off; off >>= 1) a += __shfl_down_sync(0xffffffffu, a, off);
    if (lane == 0) att[pid] = 1.0f / (1.0f + expf(-a));
}

__global__ void pool_part(const float* __restrict__ emb, const float* __restrict__ att,
                          float* __restrict__ part) {
    int b = blockIdx.x, seg = blockIdx.y, f = threadIdx.x;
    const float* p = emb + ((long)(b*NPT) + seg*128) * 128 + f;
    const float* aw = att + b*NPT + seg*128;
    float a = 0.f;
    #pragma unroll 4
    for (int n = 0; n < 128; n++) a += p[n * 128] * aw[n];
    part[(b*8 + seg) * 128 + f] = a;
}

__global__ void pool_fin(const float* __restrict__ part, float* __restrict__ e) {
    int b = blockIdx.x, t = threadIdx.x;
    float a = 0.f;
    #pragma unroll
    for (int s = 0; s < 8; s++) a += part[(b*8 + s) * 128 + t];
    e[b * 128 + t] = a;
}

// ------------------------------------------------------------------ final scoring
__global__ void final_kernel(const float* __restrict__ e, const float* __restrict__ tn_w,
                             const float* __restrict__ tn_wb, const float* __restrict__ tn_bias,
                             const float* __restrict__ fc1_w, const float* __restrict__ fc1_b,
                             const float* __restrict__ sc_w, const float* __restrict__ sc_b,
                             float* __restrict__ out) {
    __shared__ float e1s[128], e2s[128], red[128], ts[16], hs[16];
    int b = blockIdx.x, tid = threadIdx.x;
    e1s[tid] = e[b * 128 + tid];
    e2s[tid] = e[(b + 8) * 128 + tid];
    __syncthreads();
    for (int tt = 0; tt < 16; tt++) {
        float inner = 0.f;
        const float* wrow = tn_w + (long)tid * 128 * 16 + tt;
        for (int gI = 0; gI < 128; gI++) inner += wrow[gI * 16] * e2s[gI];
        red[tid] = e1s[tid] * inner;
        __syncthreads();
        for (int s2 = 64; s2; s2 >>= 1) {
            if (tid < s2) red[tid] += red[tid + s2];
            __syncthreads();
        }
        if (tid == 0) ts[tt] = red[0];
        __syncthreads();
    }
    if (tid < 16) {
        float blk = 0.f;
        for (int c = 0; c < 128; c++) blk += tn_wb[tid * 256 + c] * e1s[c];
        for (int c = 0; c < 128; c++) blk += tn_wb[tid * 256 + 128 + c] * e2s[c];
        float v = ts[tid] + blk + tn_bias[tid];
        ts[tid] = v > 0.f ? v : 0.f;
    }
    __syncthreads();
    if (tid < 16) {
        float h = fc1_b[tid];
        for (int u2 = 0; u2 < 16; u2++) h += fc1_w[tid * 16 + u2] * ts[u2];
        hs[tid] = h > 0.f ? h : 0.f;
    }
    __syncthreads();
    if (tid == 0) {
        float z = sc_b[0];
        for (int u2 = 0; u2 < 16; u2++) z += sc_w[u2] * hs[u2];
        out[b] = 1.0f / (1.0f + expf(-z));
    }
}

// ------------------------------------------------------------------ host
template <typename T>
static float* symaddr(T& sym_) {
    void* p = nullptr;
    cudaGetSymbolAddress(&p, sym_);
    return (float*)p;
}

extern "C" void kernel_launch(void* const* d_in, const int* in_sizes, int n_in,
                              void* d_out, int out_size) {
    (void)in_sizes; (void)n_in; (void)out_size;
    const float* f1    = (const float*)d_in[0];
    const float* f2    = (const float*)d_in[1];
    const float* sw1   = (const float*)d_in[2];
    const float* sg1   = (const float*)d_in[3];
    const float* sb1   = (const float*)d_in[4];
    const float* fw1   = (const float*)d_in[5];
    const float* fg1   = (const float*)d_in[6];
    const float* fb1   = (const float*)d_in[7];
    const float* sw2   = (const float*)d_in[8];
    const float* sg2   = (const float*)d_in[9];
    const float* sb2   = (const float*)d_in[10];
    const float* fw2   = (const float*)d_in[11];
    const float* fg2   = (const float*)d_in[12];
    const float* fb2   = (const float*)d_in[13];
    const float* sw3   = (const float*)d_in[14];
    const float* sg3   = (const float*)d_in[15];
    const float* sb3   = (const float*)d_in[16];
    const float* fw3   = (const float*)d_in[17];
    const float* fg3   = (const float*)d_in[18];
    const float* fb3   = (const float*)d_in[19];
    const float* ew    = (const float*)d_in[20];
    const float* eg    = (const float*)d_in[21];
    const float* ebv   = (const float*)d_in[22];
    const float* att_w = (const float*)d_in[23];
    const float* tn_w  = (const float*)d_in[24];
    const float* tn_wb = (const float*)d_in[25];
    const float* tn_b  = (const float*)d_in[26];
    const float* fc1_w = (const float*)d_in[27];
    const float* fc1_b = (const float*)d_in[28];
    const float* sc_w  = (const float*)d_in[29];
    const float* sc_b  = (const float*)d_in[30];
    float* out = (float*)d_out;

    unsigned* negp = (unsigned*)symaddr(g_neg);
    int*   idxp  = (int*)symaddr(g_idx);
    float* x0p   = symaddr(g_x0);
    float* s0p   = symaddr(g_s0);
    float* hAp   = symaddr(g_hA);
    float* hBp   = symaddr(g_hB);
    float* h3p   = symaddr(g_h3);
    float* embp  = symaddr(g_emb);
    float* partp = symaddr(g_part);
    float* gcp   = symaddr(g_gc);
    float* ep    = symaddr(g_e);

    unsigned* negB = negp + (size_t)NROW * NPT;
    int* idxB = idxp + NROW * KNN;
    float* hA_B = hAp + NROW * 64;

    const int SM_C2 = (2*64*66   + 8*21*68) * 4 + 8*KNN*4;    // conv<64,64,64,8,256,1>
    const int SM_C3 = (2*128*66  + 8*21*68) * 4 + 8*KNN*4;    // conv<64,64,128,8,512,1>
    const int SM_C4 = (2*64*130  + 16*21*68) * 4 + 16*KNN*4;  // conv<128,128,64,16,512,2>
    const int SM_EW = (256*128 + 8*256) * 4;

    cudaFuncSetAttribute(conv_kernel<64,64,64,8,256,1>,    cudaFuncAttributeMaxDynamicSharedMemorySize, SM_C2);
    cudaFuncSetAttribute(conv_kernel<64,64,128,8,512,1>,   cudaFuncAttributeMaxDynamicSharedMemorySize, SM_C3);
    cudaFuncSetAttribute(conv_kernel<128,128,64,16,512,2>, cudaFuncAttributeMaxDynamicSharedMemorySize, SM_C4);
    cudaFuncSetAttribute(emb_kernel,                       cudaFuncAttributeMaxDynamicSharedMemorySize, SM_EW);

    static cudaStream_t sB = 0;
    static cudaEvent_t evFork = 0, evJoin = 0;
    if (!sB) {
        cudaStreamCreateWithFlags(&sB, cudaStreamNonBlocking);
        cudaEventCreateWithFlags(&evFork, cudaEventDisableTiming);
        cudaEventCreateWithFlags(&evJoin, cudaEventDisableTiming);
    }

    transposeX_kernel<<<(NB*3*NPT + 255) / 256, 256>>>(f1, f2, x0p);
    transposeS_kernel<<<dim3(NPT/32, 4, NB), dim3(32, 8)>>>(f1, f2, s0p);
    cudaEventRecord(evFork, 0);
    cudaStreamWaitEvent(sB, evFork, 0);

    // ---- layer 1: stream 0 = fused xyz knn+conv, then sem batches [0,SPL);
    //               stream sB = sem batches [SPL,NB) ----
    knnconv1_kernel<<<NROW/16, 512>>>(x0p, sw1, sg1, sb1, hAp);

    dist_kernel<128><<<dim3(8,8,SPL), 256>>>(s0p, negB);
    topk_kernel<<<SPL*NPT/8, 256>>>(negB, idxB);
    conv_kernel<128,128,64,16,512,2><<<SPL*NPT/16, 512, SM_C4>>>(s0p, idxB, fw1, fw1, fg1, fg1, fb1, fb1, hA_B);

    {
        const int RB = NB - SPL;   // 9 batches on sB
        const float* s0q = s0p + (size_t)SPL * NPT * 128;
        unsigned* negq = negB + (size_t)SPL * NPT * NPT;
        int* idxq = idxB + SPL * NPT * KNN;
        float* hAq = hA_B + SPL * NPT * 64;
        dist_kernel<128><<<dim3(8,8,RB), 256, 0, sB>>>(s0q, negq);
        topk_kernel<<<RB*NPT/8, 256, 0, sB>>>(negq, idxq);
        conv_kernel<128,128,64,16,512,2><<<RB*NPT/16, 512, SM_C4, sB>>>(s0q, idxq, fw1, fw1, fg1, fg1, fb1, fb1, hAq);
    }

    cudaEventRecord(evJoin, sB);
    cudaStreamWaitEvent(0, evJoin, 0);

    // ---- layer 2 (merged NB2, 64 -> 64) ----
    dist_kernel<64><<<dim3(8,8,NB2), 256>>>(hAp, negp);
    topk_kernel<<<NROW2/8, 256>>>(negp, idxp);
    conv_kernel<64,64,64,8,256,1><<<NB2*NPT/8, 256, SM_C2>>>(hAp, idxp, sw2, fw2, sg2, fg2, sb2, fb2, hBp);

    // ---- layer 3 (merged NB2, 64 -> 128) ----
    dist_kernel<64><<<dim3(8,8,NB2), 256>>>(hBp, negp);
    topk_kernel<<<NROW2/8, 256>>>(negp, idxp);
    conv_kernel<64,64,128,8,512,1><<<NB2*NPT/8, 512, SM_C3>>>(hBp, idxp, sw3, fw3, sg3, fg3, sb3, fb3, h3p);

    // ---- fuse + attention (all 16 batches) ----
    emb_kernel<<<NROW/128, 256, SM_EW>>>(h3p, h3p + NROW*128, ew, eg, ebv, embp);

    float* att_out = out + 8;                       // att1 (b 0..7) then att2 (b 8..15), contiguous
    gcfused_kernel<<<NB, 1024>>>(embp, att_w, gcp);
    sc_kernel<<<NROW/4, 128>>>(embp, gcp, att_out);
    pool_part<<<dim3(NB, 8), 128>>>(embp, att_out, partp);
    pool_fin<<<NB, 128>>>(partp, ep);

    final_kernel<<<BB, 128>>>(ep, tn_w, tn_wb, tn_b, fc1_w, fc1_b, sc_w, sc_b, out);
}